// round 2
// baseline (speedup 1.0000x reference)
#include <cuda_runtime.h>

#define NN 50000
#define EE 800000
#define HH 128
#define ED 16
#define SP 132
#define XP 264

// ---------------- scratch (device globals: no allocations allowed) ----------
__device__ int   g_is64;
__device__ int   g_src[EE];
__device__ int   g_dst[EE];
__device__ float g_A[NN * HH];     // h @ We1[0:128]
__device__ float g_B[NN * HH];     // h @ We1[128:256]
__device__ float g_agg[NN * HH];   // segment-sum of m

__device__ __forceinline__ float siluf(float v) {
    return __fdividef(v, 1.0f + __expf(-v));
}

// ---------------- index dtype detection + conversion ------------------------
__global__ void k_detect(const void* ei) {
    if (blockIdx.x == 0 && threadIdx.x == 0) {
        const int* p = (const int*)ei;
        int acc = 0;
        for (int i = 0; i < 64; i++) acc |= p[2 * i + 1];
        g_is64 = (acc == 0) ? 1 : 0;  // int64 values < 2^31 -> high words all 0
    }
}

__global__ void k_convert(const void* ei) {
    int e = blockIdx.x * blockDim.x + threadIdx.x;
    if (e >= EE) return;
    if (g_is64) {
        const long long* p = (const long long*)ei;
        g_src[e] = (int)p[e];
        g_dst[e] = (int)p[EE + e];
    } else {
        const int* p = (const int*)ei;
        g_src[e] = p[e];
        g_dst[e] = p[EE + e];
    }
}

// ---------------- init: zero agg, x_out = x ---------------------------------
__global__ void k_init(const float* __restrict__ x, float* __restrict__ outx) {
    for (int i = blockIdx.x * blockDim.x + threadIdx.x; i < NN * HH;
         i += gridDim.x * blockDim.x) {
        g_agg[i] = 0.0f;
        if (i < NN * 3) outx[i] = x[i];
    }
}

// ---------------- node pre-GEMM: A = h@We1[0:128], B = h@We1[128:256] -------
__global__ __launch_bounds__(256, 2) void k_node_pre(
    const float* __restrict__ h, const float* __restrict__ We1) {
    extern __shared__ float sm[];
    float* ht = sm;            // 64*SP
    float* wt = sm + 64 * SP;  // 16*SP
    int tid = threadIdx.x;
    int n0 = blockIdx.x * 64;

#pragma unroll
    for (int v = 0; v < 8; v++) {
        int idx = tid * 32 + v * 4;
        int r = idx >> 7, c = idx & 127;
        float4 val = make_float4(0.f, 0.f, 0.f, 0.f);
        if (n0 + r < NN) val = *(const float4*)&h[(n0 + r) * 128 + c];
        *(float4*)&ht[r * SP + c] = val;
    }
    int rg = tid >> 4, cg = tid & 15;
    int r0 = rg * 4, c0 = cg * 8;

    for (int half = 0; half < 2; half++) {
        const float* W = We1 + half * 128 * 128;
        float acc[4][8];
#pragma unroll
        for (int i = 0; i < 4; i++)
#pragma unroll
            for (int j = 0; j < 8; j++) acc[i][j] = 0.f;

        for (int k0 = 0; k0 < 128; k0 += 16) {
            __syncthreads();
            int lin = tid * 8;
            int row = lin >> 7, col = lin & 127;
            *(float4*)&wt[row * SP + col] = *(const float4*)&W[(k0 + row) * 128 + col];
            *(float4*)&wt[row * SP + col + 4] = *(const float4*)&W[(k0 + row) * 128 + col + 4];
            __syncthreads();
#pragma unroll
            for (int kk = 0; kk < 16; kk++) {
                float sv[4];
#pragma unroll
                for (int i = 0; i < 4; i++) sv[i] = ht[(r0 + i) * SP + k0 + kk];
                float4 w0 = *(float4*)&wt[kk * SP + c0];
                float4 w1 = *(float4*)&wt[kk * SP + c0 + 4];
                float wv[8] = {w0.x, w0.y, w0.z, w0.w, w1.x, w1.y, w1.z, w1.w};
#pragma unroll
                for (int i = 0; i < 4; i++)
#pragma unroll
                    for (int j = 0; j < 8; j++) acc[i][j] += sv[i] * wv[j];
            }
        }
        float* out = half ? g_B : g_A;
#pragma unroll
        for (int i = 0; i < 4; i++) {
            if (n0 + r0 + i < NN) {
                *(float4*)&out[(n0 + r0 + i) * 128 + c0] =
                    make_float4(acc[i][0], acc[i][1], acc[i][2], acc[i][3]);
                *(float4*)&out[(n0 + r0 + i) * 128 + c0 + 4] =
                    make_float4(acc[i][4], acc[i][5], acc[i][6], acc[i][7]);
            }
        }
    }
}

// ---------------- fused edge kernel -----------------------------------------
__global__ __launch_bounds__(256, 2) void k_edge(
    const float* __restrict__ x, const float* __restrict__ ea,
    const float* __restrict__ We1, const float* __restrict__ be1,
    const float* __restrict__ We2, const float* __restrict__ be2,
    const float* __restrict__ Wx1, const float* __restrict__ bx1,
    const float* __restrict__ Wx2, const float* __restrict__ bx2,
    float* __restrict__ outx) {
    extern __shared__ float sm[];
    float* s    = sm;                 // 64*SP
    float* mm   = s + 64 * SP;        // 64*SP
    float* wt   = mm + 64 * SP;       // 16*SP
    float* w1e  = wt + 16 * SP;       // 16*SP (We1 rows 256..271)
    float* be1s = w1e + 16 * SP;      // 128
    float* be2s = be1s + 128;
    float* bx1s = be2s + 128;
    float* wds  = bx1s + 128;         // We1 row 272 (dist)
    float* wx2s = wds + 128;
    float* sdist = wx2s + 128;        // 64
    float* sgx = sdist + 64;
    float* sgy = sgx + 64;
    float* sgz = sgy + 64;
    float* sgate = sgz + 64;
    float* sea = sgate + 64;          // 64*16
    int* ssrc = (int*)(sea + 64 * 16);
    int* sdst = ssrc + 64;

    int tid = threadIdx.x;
    int e0 = blockIdx.x * 64;

    if (tid < 128) {
        be1s[tid] = be1[tid];
        be2s[tid] = be2[tid];
        bx1s[tid] = bx1[tid];
        wds[tid] = We1[272 * 128 + tid];
        wx2s[tid] = Wx2[tid];
    }
    {
        int lin = tid * 8;
        int row = lin >> 7, col = lin & 127;
        *(float4*)&w1e[row * SP + col] = *(const float4*)&We1[(256 + row) * 128 + col];
        *(float4*)&w1e[row * SP + col + 4] = *(const float4*)&We1[(256 + row) * 128 + col + 4];
    }
    if (tid < 64) {
        int e = e0 + tid;
        int si = g_src[e], di = g_dst[e];
        ssrc[tid] = si;
        sdst[tid] = di;
        float dx = x[di * 3 + 0] - x[si * 3 + 0];
        float dy = x[di * 3 + 1] - x[si * 3 + 1];
        float dz = x[di * 3 + 2] - x[si * 3 + 2];
        float ss2 = dx * dx + dy * dy + dz * dz;
        sdist[tid] = sqrtf(ss2 + 1e-9f);
        float rn = __fdividef(1.0f, sqrtf(ss2) + 1e-9f);
        sgx[tid] = dx * rn;
        sgy[tid] = dy * rn;
        sgz[tid] = dz * rn;
        sgate[tid] = bx2[0];
    }
    {
        int e_l = tid >> 2, j0 = (tid & 3) * 4;
        *(float4*)&sea[e_l * 16 + j0] = *(const float4*)&ea[(e0 + e_l) * 16 + j0];
    }
    __syncthreads();

    // ---- phase 1: s = silu(A[src]+B[dst]+ea@We1e + dist*wd + be1) ----
    {
        int e_l = tid >> 2, q = tid & 3;
        int si = ssrc[e_l], di = sdst[e_l];
        float d = sdist[e_l];
        float eav[16];
#pragma unroll
        for (int j = 0; j < 16; j++) eav[j] = sea[e_l * 16 + j];
        const float4* A4 = (const float4*)g_A;
        const float4* B4 = (const float4*)g_B;
#pragma unroll
        for (int i = 0; i < 8; i++) {
            int c = i * 16 + q * 4;  // q*4 keeps smem accesses conflict-free
            float4 a = A4[si * 32 + i * 4 + q];
            float4 b = B4[di * 32 + i * 4 + q];
            float4 bb = *(const float4*)&be1s[c];
            float4 wd4 = *(const float4*)&wds[c];
            float av[4] = {a.x + b.x + bb.x + d * wd4.x, a.y + b.y + bb.y + d * wd4.y,
                           a.z + b.z + bb.z + d * wd4.z, a.w + b.w + bb.w + d * wd4.w};
#pragma unroll
            for (int j = 0; j < 16; j++) {
                float4 w = *(const float4*)&w1e[j * SP + c];
                av[0] += eav[j] * w.x;
                av[1] += eav[j] * w.y;
                av[2] += eav[j] * w.z;
                av[3] += eav[j] * w.w;
            }
            float4 o = make_float4(siluf(av[0]), siluf(av[1]), siluf(av[2]), siluf(av[3]));
            *(float4*)&s[e_l * SP + c] = o;
        }
    }

    int rg = tid >> 4, cg = tid & 15;
    int r0 = rg * 4, c0 = cg * 8;

    // ---- GEMM1: mm = s @ We2 + be2 ----
    {
        float acc[4][8];
#pragma unroll
        for (int i = 0; i < 4; i++)
#pragma unroll
            for (int j = 0; j < 8; j++) acc[i][j] = be2s[c0 + j];

        for (int k0 = 0; k0 < 128; k0 += 16) {
            __syncthreads();
            int lin = tid * 8;
            int row = lin >> 7, col = lin & 127;
            *(float4*)&wt[row * SP + col] = *(const float4*)&We2[(k0 + row) * 128 + col];
            *(float4*)&wt[row * SP + col + 4] = *(const float4*)&We2[(k0 + row) * 128 + col + 4];
            __syncthreads();
#pragma unroll
            for (int kk = 0; kk < 16; kk++) {
                float sv[4];
#pragma unroll
                for (int i = 0; i < 4; i++) sv[i] = s[(r0 + i) * SP + k0 + kk];
                float4 w0 = *(float4*)&wt[kk * SP + c0];
                float4 w1 = *(float4*)&wt[kk * SP + c0 + 4];
                float wv[8] = {w0.x, w0.y, w0.z, w0.w, w1.x, w1.y, w1.z, w1.w};
#pragma unroll
                for (int i = 0; i < 4; i++)
#pragma unroll
                    for (int j = 0; j < 8; j++) acc[i][j] += sv[i] * wv[j];
            }
        }
#pragma unroll
        for (int i = 0; i < 4; i++) {
            *(float4*)&mm[(r0 + i) * SP + c0] =
                make_float4(acc[i][0], acc[i][1], acc[i][2], acc[i][3]);
            *(float4*)&mm[(r0 + i) * SP + c0 + 4] =
                make_float4(acc[i][4], acc[i][5], acc[i][6], acc[i][7]);
        }
    }

    // ---- GEMM2: gate += silu(mm@Wx1+bx1) . wx2 ----
    {
        float acc[4][8];
#pragma unroll
        for (int i = 0; i < 4; i++)
#pragma unroll
            for (int j = 0; j < 8; j++) acc[i][j] = bx1s[c0 + j];

        for (int k0 = 0; k0 < 128; k0 += 16) {
            __syncthreads();  // first iter: also makes mm visible to all
            int lin = tid * 8;
            int row = lin >> 7, col = lin & 127;
            *(float4*)&wt[row * SP + col] = *(const float4*)&Wx1[(k0 + row) * 128 + col];
            *(float4*)&wt[row * SP + col + 4] = *(const float4*)&Wx1[(k0 + row) * 128 + col + 4];
            __syncthreads();
#pragma unroll
            for (int kk = 0; kk < 16; kk++) {
                float sv[4];
#pragma unroll
                for (int i = 0; i < 4; i++) sv[i] = mm[(r0 + i) * SP + k0 + kk];
                float4 w0 = *(float4*)&wt[kk * SP + c0];
                float4 w1 = *(float4*)&wt[kk * SP + c0 + 4];
                float wv[8] = {w0.x, w0.y, w0.z, w0.w, w1.x, w1.y, w1.z, w1.w};
#pragma unroll
                for (int i = 0; i < 4; i++)
#pragma unroll
                    for (int j = 0; j < 8; j++) acc[i][j] += sv[i] * wv[j];
            }
        }
#pragma unroll
        for (int i = 0; i < 4; i++) {
            float p = 0.f;
#pragma unroll
            for (int j = 0; j < 8; j++) p += siluf(acc[i][j]) * wx2s[c0 + j];
            atomicAdd(&sgate[r0 + i], p);
        }
    }
    __syncthreads();

    // ---- scatter: agg[dst] += m ; x_out[dst] += dir * gate ----
    {
        int e_l = tid >> 2, q = tid & 3;
        int di = sdst[e_l];
        float* dstp = &g_agg[di * 128 + q * 32];
#pragma unroll
        for (int i = 0; i < 8; i++) {
            float4 v = *(float4*)&mm[e_l * SP + q * 32 + i * 4];
            atomicAdd(dstp + i * 4 + 0, v.x);
            atomicAdd(dstp + i * 4 + 1, v.y);
            atomicAdd(dstp + i * 4 + 2, v.z);
            atomicAdd(dstp + i * 4 + 3, v.w);
        }
    }
    if (tid < 64) {
        float gte = sgate[tid];
        int di = sdst[tid];
        atomicAdd(&outx[di * 3 + 0], sgx[tid] * gte);
        atomicAdd(&outx[di * 3 + 1], sgy[tid] * gte);
        atomicAdd(&outx[di * 3 + 2], sgz[tid] * gte);
    }
}

// ---------------- node update: LN(h + phi_h([h,agg])) -----------------------
__global__ __launch_bounds__(256, 2) void k_node_upd(
    const float* __restrict__ h, const float* __restrict__ Wh1,
    const float* __restrict__ bh1, const float* __restrict__ Wh2,
    const float* __restrict__ bh2, const float* __restrict__ lng,
    const float* __restrict__ lnb, float* __restrict__ outh) {
    extern __shared__ float sm[];
    float* xt = sm;             // 64*XP  ([h | agg])
    float* tt = xt + 64 * XP;   // 64*SP
    float* wt = tt + 64 * SP;   // 16*SP
    float* bh1s = wt + 16 * SP;
    float* bh2s = bh1s + 128;
    float* lngs = bh2s + 128;
    float* lnbs = lngs + 128;
    float* ssum = lnbs + 128;   // 64
    float* ssq = ssum + 64;     // 64

    int tid = threadIdx.x;
    int n0 = blockIdx.x * 64;
    if (tid < 128) {
        bh1s[tid] = bh1[tid];
        bh2s[tid] = bh2[tid];
        lngs[tid] = lng[tid];
        lnbs[tid] = lnb[tid];
    }
    if (tid < 64) {
        ssum[tid] = 0.f;
        ssq[tid] = 0.f;
    }
#pragma unroll
    for (int v = 0; v < 16; v++) {
        int idx = tid * 64 + v * 4;
        int r = idx >> 8, c = idx & 255;
        float4 val = make_float4(0.f, 0.f, 0.f, 0.f);
        if (n0 + r < NN) {
            if (c < 128)
                val = *(const float4*)&h[(n0 + r) * 128 + c];
            else
                val = *(const float4*)&g_agg[(n0 + r) * 128 + (c - 128)];
        }
        *(float4*)&xt[r * XP + c] = val;
    }
    __syncthreads();

    int rg = tid >> 4, cg = tid & 15;
    int r0 = rg * 4, c0 = cg * 8;

    // GEMM1: tt = silu([h,agg]@Wh1 + bh1), K=256
    {
        float acc[4][8];
#pragma unroll
        for (int i = 0; i < 4; i++)
#pragma unroll
            for (int j = 0; j < 8; j++) acc[i][j] = bh1s[c0 + j];

        for (int k0 = 0; k0 < 256; k0 += 16) {
            __syncthreads();
            int lin = tid * 8;
            int row = lin >> 7, col = lin & 127;
            *(float4*)&wt[row * SP + col] = *(const float4*)&Wh1[(k0 + row) * 128 + col];
            *(float4*)&wt[row * SP + col + 4] = *(const float4*)&Wh1[(k0 + row) * 128 + col + 4];
            __syncthreads();
#pragma unroll
            for (int kk = 0; kk < 16; kk++) {
                float sv[4];
#pragma unroll
                for (int i = 0; i < 4; i++) sv[i] = xt[(r0 + i) * XP + k0 + kk];
                float4 w0 = *(float4*)&wt[kk * SP + c0];
                float4 w1 = *(float4*)&wt[kk * SP + c0 + 4];
                float wv[8] = {w0.x, w0.y, w0.z, w0.w, w1.x, w1.y, w1.z, w1.w};
#pragma unroll
                for (int i = 0; i < 4; i++)
#pragma unroll
                    for (int j = 0; j < 8; j++) acc[i][j] += sv[i] * wv[j];
            }
        }
#pragma unroll
        for (int i = 0; i < 4; i++) {
            *(float4*)&tt[(r0 + i) * SP + c0] =
                make_float4(siluf(acc[i][0]), siluf(acc[i][1]), siluf(acc[i][2]), siluf(acc[i][3]));
            *(float4*)&tt[(r0 + i) * SP + c0 + 4] =
                make_float4(siluf(acc[i][4]), siluf(acc[i][5]), siluf(acc[i][6]), siluf(acc[i][7]));
        }
    }

    // GEMM2: dh = tt@Wh2 + bh2, K=128
    float acc2[4][8];
    {
#pragma unroll
        for (int i = 0; i < 4; i++)
#pragma unroll
            for (int j = 0; j < 8; j++) acc2[i][j] = bh2s[c0 + j];

        for (int k0 = 0; k0 < 128; k0 += 16) {
            __syncthreads();
            int lin = tid * 8;
            int row = lin >> 7, col = lin & 127;
            *(float4*)&wt[row * SP + col] = *(const float4*)&Wh2[(k0 + row) * 128 + col];
            *(float4*)&wt[row * SP + col + 4] = *(const float4*)&Wh2[(k0 + row) * 128 + col + 4];
            __syncthreads();
#pragma unroll
            for (int kk = 0; kk < 16; kk++) {
                float sv[4];
#pragma unroll
                for (int i = 0; i < 4; i++) sv[i] = tt[(r0 + i) * SP + k0 + kk];
                float4 w0 = *(float4*)&wt[kk * SP + c0];
                float4 w1 = *(float4*)&wt[kk * SP + c0 + 4];
                float wv[8] = {w0.x, w0.y, w0.z, w0.w, w1.x, w1.y, w1.z, w1.w};
#pragma unroll
                for (int i = 0; i < 4; i++)
#pragma unroll
                    for (int j = 0; j < 8; j++) acc2[i][j] += sv[i] * wv[j];
            }
        }
    }

    // v = h + dh; row stats
#pragma unroll
    for (int i = 0; i < 4; i++) {
        float p = 0.f, p2 = 0.f;
#pragma unroll
        for (int j = 0; j < 8; j++) {
            float v = xt[(r0 + i) * XP + c0 + j] + acc2[i][j];
            p += v;
            p2 += v * v;
        }
        atomicAdd(&ssum[r0 + i], p);
        atomicAdd(&ssq[r0 + i], p2);
    }
    __syncthreads();
#pragma unroll
    for (int i = 0; i < 4; i++) {
        int n = n0 + r0 + i;
        if (n < NN) {
            float mean = ssum[r0 + i] * (1.0f / 128.0f);
            float var = ssq[r0 + i] * (1.0f / 128.0f) - mean * mean;
            float rstd = rsqrtf(var + 1e-5f);
            float o[8];
#pragma unroll
            for (int j = 0; j < 8; j++) {
                float v = xt[(r0 + i) * XP + c0 + j] + acc2[i][j];
                o[j] = (v - mean) * rstd * lngs[c0 + j] + lnbs[c0 + j];
            }
            *(float4*)&outh[n * 128 + c0] = make_float4(o[0], o[1], o[2], o[3]);
            *(float4*)&outh[n * 128 + c0 + 4] = make_float4(o[4], o[5], o[6], o[7]);
        }
    }
}

// ---------------- launcher ---------------------------------------------------
extern "C" void kernel_launch(void* const* d_in, const int* in_sizes, int n_in,
                              void* d_out, int out_size) {
    const float* h = (const float*)d_in[0];
    const float* x = (const float*)d_in[1];
    const void* ei = d_in[2];
    const float* ea = (const float*)d_in[3];
    const float* We1 = (const float*)d_in[4];
    const float* be1 = (const float*)d_in[5];
    const float* We2 = (const float*)d_in[6];
    const float* be2 = (const float*)d_in[7];
    const float* Wh1 = (const float*)d_in[8];
    const float* bh1 = (const float*)d_in[9];
    const float* Wh2 = (const float*)d_in[10];
    const float* bh2 = (const float*)d_in[11];
    const float* Wx1 = (const float*)d_in[12];
    const float* bx1 = (const float*)d_in[13];
    const float* Wx2 = (const float*)d_in[14];
    const float* bx2 = (const float*)d_in[15];
    const float* lng = (const float*)d_in[16];
    const float* lnb = (const float*)d_in[17];

    float* outh = (float*)d_out;
    float* outx = outh + (size_t)NN * HH;

    const int SMEM_EDGE = 92928;
    const int SMEM_UPD = 112384;
    const int SMEM_PRE = 42240;
    cudaFuncSetAttribute(k_edge, cudaFuncAttributeMaxDynamicSharedMemorySize, SMEM_EDGE);
    cudaFuncSetAttribute(k_node_upd, cudaFuncAttributeMaxDynamicSharedMemorySize, SMEM_UPD);
    cudaFuncSetAttribute(k_node_pre, cudaFuncAttributeMaxDynamicSharedMemorySize, SMEM_PRE);

    k_detect<<<1, 32>>>(ei);
    k_convert<<<(EE + 255) / 256, 256>>>(ei);
    k_init<<<1024, 256>>>(x, outx);
    k_node_pre<<<(NN + 63) / 64, 256, SMEM_PRE>>>(h, We1);
    k_edge<<<EE / 64, 256, SMEM_EDGE>>>(x, ea, We1, be1, We2, be2, Wx1, bx1, Wx2,
                                        bx2, outx);
    k_node_upd<<<(NN + 63) / 64, 256, SMEM_UPD>>>(h, Wh1, bh1, Wh2, bh2, lng, lnb,
                                                  outh);
}

// round 3
// speedup vs baseline: 3.4147x; 3.4147x over previous
#include <cuda_runtime.h>

#define NN 50000
#define EE 800000
#define HH 128
#define ED 16
#define SP 132

// ---------------- scratch (device globals) ----------------------------------
__device__ int   g_is64;
__device__ int   g_src[EE];
__device__ int   g_dst[EE];
__device__ float g_A[NN * HH];     // h @ We1[0:128]
__device__ float g_B[NN * HH];     // h @ We1[128:256]
__device__ float g_agg[NN * HH];   // segment-sum of m

__device__ __forceinline__ float siluf(float v) {
    return __fdividef(v, 1.0f + __expf(-v));
}

__device__ __forceinline__ unsigned f2tf(float v) {
    unsigned u;
    asm("cvt.rna.tf32.f32 %0, %1;" : "=r"(u) : "f"(v));
    return u;
}

__device__ __forceinline__ void mma8(float* c, const unsigned* a, const unsigned* b) {
    asm volatile(
        "mma.sync.aligned.m16n8k8.row.col.f32.tf32.tf32.f32 "
        "{%0,%1,%2,%3},{%4,%5,%6,%7},{%8,%9},{%0,%1,%2,%3};"
        : "+f"(c[0]), "+f"(c[1]), "+f"(c[2]), "+f"(c[3])
        : "r"(a[0]), "r"(a[1]), "r"(a[2]), "r"(a[3]), "r"(b[0]), "r"(b[1]));
}

// Stage W (gmem, row-major K=128 x N=128) into smem transposed WT[n][k] (pad SP),
// pre-converted to tf32. Lane mapping n=lane%8, k=lane/8 -> conflict-free STS.
__device__ __forceinline__ void stage_wt(float* wt, const float* __restrict__ W, int tid) {
    int lane = tid & 31, warp = tid >> 5;
    int n_lo = lane & 7, k_l = lane >> 3;
#pragma unroll
    for (int p = 0; p < 2; p++) {
        int n = n_lo + 8 * (2 * warp + p);
#pragma unroll 4
        for (int q = 0; q < 32; q++) {
            int k = k_l + 4 * q;
            float v = W[k * 128 + n];
            wt[n * SP + k] = __uint_as_float(f2tf(v));
        }
    }
}

// Warp-tiled (M=32, N=64) K=128 tf32 GEMM k-loop. sA fp32 [rows][SP]; wt tf32 [128][SP].
__device__ __forceinline__ void gemm_kloop(const float* sA, const float* wt,
                                           int mrow, int ncol, int lane,
                                           float acc[2][8][4]) {
    int g = lane >> 2, tg = lane & 3;
    const float* a0p = sA + (mrow + g) * SP + tg;
    const float* b0p = wt + (ncol + g) * SP + tg;
#pragma unroll 4
    for (int kk = 0; kk < 16; kk++) {
        int k0 = kk * 8;
        unsigned a[2][4];
#pragma unroll
        for (int mt = 0; mt < 2; mt++) {
            const float* ap = a0p + mt * 16 * SP + k0;
            a[mt][0] = f2tf(ap[0]);
            a[mt][1] = f2tf(ap[8 * SP]);
            a[mt][2] = f2tf(ap[4]);
            a[mt][3] = f2tf(ap[8 * SP + 4]);
        }
#pragma unroll
        for (int nt = 0; nt < 8; nt++) {
            const float* bp = b0p + nt * 8 * SP + k0;
            unsigned b[2];
            b[0] = __float_as_uint(bp[0]);
            b[1] = __float_as_uint(bp[4]);
            mma8(acc[0][nt], a[0], b);
            mma8(acc[1][nt], a[1], b);
        }
    }
}

__device__ __forceinline__ void acc_init_bias(float acc[2][8][4], const float* bias,
                                              int ncol, int tg) {
#pragma unroll
    for (int nt = 0; nt < 8; nt++) {
        int cb = ncol + nt * 8 + tg * 2;
        float b0v = bias[cb], b1v = bias[cb + 1];
#pragma unroll
        for (int mt = 0; mt < 2; mt++) {
            acc[mt][nt][0] = b0v;
            acc[mt][nt][1] = b1v;
            acc[mt][nt][2] = b0v;
            acc[mt][nt][3] = b1v;
        }
    }
}

// ---------------- index dtype detection + conversion ------------------------
__global__ void k_detect(const void* ei) {
    if (blockIdx.x == 0 && threadIdx.x == 0) {
        const int* p = (const int*)ei;
        int acc = 0;
        for (int i = 0; i < 64; i++) acc |= p[2 * i + 1];
        g_is64 = (acc == 0) ? 1 : 0;
    }
}

__global__ void k_convert(const void* ei) {
    int e = blockIdx.x * blockDim.x + threadIdx.x;
    if (e >= EE) return;
    if (g_is64) {
        const long long* p = (const long long*)ei;
        g_src[e] = (int)p[e];
        g_dst[e] = (int)p[EE + e];
    } else {
        const int* p = (const int*)ei;
        g_src[e] = p[e];
        g_dst[e] = p[EE + e];
    }
}

// ---------------- init: zero agg, x_out = x ---------------------------------
__global__ void k_init(const float* __restrict__ x, float* __restrict__ outx) {
    for (int i = blockIdx.x * blockDim.x + threadIdx.x; i < NN * HH;
         i += gridDim.x * blockDim.x) {
        g_agg[i] = 0.0f;
        if (i < NN * 3) outx[i] = x[i];
    }
}

// ---------------- node pre-GEMM (tensor): A = h@We1a, B = h@We1b ------------
__global__ __launch_bounds__(256, 1) void k_node_pre(
    const float* __restrict__ h, const float* __restrict__ We1) {
    extern __shared__ float sm[];
    float* ht = sm;             // 128*SP
    float* wt = ht + 128 * SP;  // 128*SP

    int tid = threadIdx.x, lane = tid & 31, warp = tid >> 5;
    int n0 = blockIdx.x * 128;

#pragma unroll
    for (int v = 0; v < 16; v++) {
        int f = v * 256 + tid;
        int r = f >> 5, c4 = (f & 31) * 4;
        float4 val = make_float4(0.f, 0.f, 0.f, 0.f);
        if (n0 + r < NN) val = *(const float4*)&h[(n0 + r) * 128 + c4];
        *(float4*)&ht[r * SP + c4] = val;
    }
    stage_wt(wt, We1, tid);
    __syncthreads();

    int mrow = (warp >> 1) * 32, ncol = (warp & 1) * 64;
    int g = lane >> 2, tg = lane & 3;

    for (int half = 0; half < 2; half++) {
        float acc[2][8][4];
#pragma unroll
        for (int mt = 0; mt < 2; mt++)
#pragma unroll
            for (int nt = 0; nt < 8; nt++)
#pragma unroll
                for (int l = 0; l < 4; l++) acc[mt][nt][l] = 0.f;
        gemm_kloop(ht, wt, mrow, ncol, lane, acc);
        float* out = half ? g_B : g_A;
#pragma unroll
        for (int mt = 0; mt < 2; mt++)
#pragma unroll
            for (int nt = 0; nt < 8; nt++) {
                int r = mrow + mt * 16 + g;
                int cb = ncol + nt * 8 + tg * 2;
                if (n0 + r < NN)
                    *(float2*)&out[(n0 + r) * 128 + cb] =
                        make_float2(acc[mt][nt][0], acc[mt][nt][1]);
                if (n0 + r + 8 < NN)
                    *(float2*)&out[(n0 + r + 8) * 128 + cb] =
                        make_float2(acc[mt][nt][2], acc[mt][nt][3]);
            }
        if (half == 0) {
            __syncthreads();
            stage_wt(wt, We1 + 128 * 128, tid);
            __syncthreads();
        }
    }
}

// ---------------- fused edge kernel (tensor GEMMs) --------------------------
__global__ __launch_bounds__(256, 1) void k_edge(
    const float* __restrict__ x, const float* __restrict__ ea,
    const float* __restrict__ We1, const float* __restrict__ be1,
    const float* __restrict__ We2, const float* __restrict__ be2,
    const float* __restrict__ Wx1, const float* __restrict__ bx1,
    const float* __restrict__ Wx2, const float* __restrict__ bx2,
    float* __restrict__ outx) {
    extern __shared__ float sm[];
    float* s    = sm;                  // 128*SP
    float* mm   = s + 128 * SP;        // 128*SP
    float* wt   = mm + 128 * SP;       // 128*SP
    float* w1e  = wt + 128 * SP;       // 16*SP
    float* be1s = w1e + 16 * SP;       // 128
    float* be2s = be1s + 128;
    float* bx1s = be2s + 128;
    float* wds  = bx1s + 128;
    float* wx2s = wds + 128;
    float* sgate = wx2s + 128;         // 128
    float* sgx = sgate + 128;
    float* sgy = sgx + 128;
    float* sgz = sgy + 128;

    int tid = threadIdx.x, lane = tid & 31, warp = tid >> 5;
    int e0 = blockIdx.x * 128;

    if (tid < 128) {
        be1s[tid] = be1[tid];
        be2s[tid] = be2[tid];
        bx1s[tid] = bx1[tid];
        wds[tid] = We1[272 * 128 + tid];
        wx2s[tid] = Wx2[tid];
        sgate[tid] = bx2[0];
        int e = e0 + tid;
        int si = g_src[e], di = g_dst[e];
        float dx = x[di * 3 + 0] - x[si * 3 + 0];
        float dy = x[di * 3 + 1] - x[si * 3 + 1];
        float dz = x[di * 3 + 2] - x[si * 3 + 2];
        float ss2 = dx * dx + dy * dy + dz * dz;
        float rn = __fdividef(1.0f, sqrtf(ss2) + 1e-9f);
        sgx[tid] = dx * rn;
        sgy[tid] = dy * rn;
        sgz[tid] = dz * rn;
    }
#pragma unroll
    for (int v = 0; v < 2; v++) {  // We1 rows 256..271 (edge-attr block), row-major
        int f = v * 256 + tid;
        int r = f >> 5, c4 = (f & 31) * 4;
        *(float4*)&w1e[r * SP + c4] = *(const float4*)&We1[(256 + r) * 128 + c4];
    }
    stage_wt(wt, We2, tid);
    __syncthreads();

    // ---- phase 1: s = silu(A[src]+B[dst]+ea@We1e + dist*wd + be1) ----
    {
        int e_l = tid >> 1, q = tid & 1;
        int e = e0 + e_l;
        int si = g_src[e], di = g_dst[e];
        float dx = x[di * 3 + 0] - x[si * 3 + 0];
        float dy = x[di * 3 + 1] - x[si * 3 + 1];
        float dz = x[di * 3 + 2] - x[si * 3 + 2];
        float dist = sqrtf(dx * dx + dy * dy + dz * dz + 1e-9f);
        float eav[16];
#pragma unroll
        for (int j = 0; j < 4; j++) {
            float4 t4 = *(const float4*)&ea[e * 16 + j * 4];
            eav[j * 4 + 0] = t4.x; eav[j * 4 + 1] = t4.y;
            eav[j * 4 + 2] = t4.z; eav[j * 4 + 3] = t4.w;
        }
        const float4* A4 = (const float4*)g_A;
        const float4* B4 = (const float4*)g_B;
#pragma unroll
        for (int i = 0; i < 16; i++) {
            int c = q * 64 + i * 4;
            float4 a = A4[si * 32 + q * 16 + i];
            float4 b = B4[di * 32 + q * 16 + i];
            float4 bb = *(float4*)&be1s[c];
            float4 wd4 = *(float4*)&wds[c];
            float v0 = a.x + b.x + bb.x + dist * wd4.x;
            float v1 = a.y + b.y + bb.y + dist * wd4.y;
            float v2 = a.z + b.z + bb.z + dist * wd4.z;
            float v3 = a.w + b.w + bb.w + dist * wd4.w;
#pragma unroll
            for (int j = 0; j < 16; j++) {
                float4 w = *(float4*)&w1e[j * SP + c];
                v0 += eav[j] * w.x;
                v1 += eav[j] * w.y;
                v2 += eav[j] * w.z;
                v3 += eav[j] * w.w;
            }
            *(float4*)&s[e_l * SP + c] =
                make_float4(siluf(v0), siluf(v1), siluf(v2), siluf(v3));
        }
    }
    __syncthreads();

    int mrow = (warp >> 1) * 32, ncol = (warp & 1) * 64;
    int g = lane >> 2, tg = lane & 3;

    // ---- GEMM1: mm = s @ We2 + be2 (tf32 tensor) ----
    {
        float acc[2][8][4];
        acc_init_bias(acc, be2s, ncol, tg);
        gemm_kloop(s, wt, mrow, ncol, lane, acc);
#pragma unroll
        for (int mt = 0; mt < 2; mt++)
#pragma unroll
            for (int nt = 0; nt < 8; nt++) {
                int r = mrow + mt * 16 + g;
                int cb = ncol + nt * 8 + tg * 2;
                *(float2*)&mm[r * SP + cb] = make_float2(acc[mt][nt][0], acc[mt][nt][1]);
                *(float2*)&mm[(r + 8) * SP + cb] = make_float2(acc[mt][nt][2], acc[mt][nt][3]);
            }
    }
    __syncthreads();
    stage_wt(wt, Wx1, tid);
    __syncthreads();

    // ---- GEMM2: gate = sum_n silu(mm@Wx1+bx1)*wx2 ----
    {
        float acc[2][8][4];
        acc_init_bias(acc, bx1s, ncol, tg);
        gemm_kloop(mm, wt, mrow, ncol, lane, acc);
        float p[4] = {0.f, 0.f, 0.f, 0.f};
#pragma unroll
        for (int mt = 0; mt < 2; mt++)
#pragma unroll
            for (int nt = 0; nt < 8; nt++) {
                int cb = ncol + nt * 8 + tg * 2;
                float w0 = wx2s[cb], w1 = wx2s[cb + 1];
                p[mt * 2 + 0] += siluf(acc[mt][nt][0]) * w0 + siluf(acc[mt][nt][1]) * w1;
                p[mt * 2 + 1] += siluf(acc[mt][nt][2]) * w0 + siluf(acc[mt][nt][3]) * w1;
            }
#pragma unroll
        for (int i = 0; i < 4; i++) {
            p[i] += __shfl_xor_sync(0xffffffffu, p[i], 1);
            p[i] += __shfl_xor_sync(0xffffffffu, p[i], 2);
        }
        float pv = (tg == 0) ? p[0] : (tg == 1) ? p[1] : (tg == 2) ? p[2] : p[3];
        atomicAdd(&sgate[mrow + tg * 8 + g], pv);
    }
    __syncthreads();

    // ---- scatter: agg[dst] += m (vector red), x_out[dst] += dir*gate ----
    {
        int e_l = tid >> 1, q = tid & 1;
        int di = g_dst[e0 + e_l];
        float* dstp = &g_agg[di * 128 + q * 64];
        const float* mp = &mm[e_l * SP + q * 64];
#pragma unroll
        for (int i = 0; i < 16; i++) {
            float4 v = *(const float4*)&mp[i * 4];
            asm volatile("red.global.add.v4.f32 [%0], {%1,%2,%3,%4};"
                         :: "l"(dstp + i * 4), "f"(v.x), "f"(v.y), "f"(v.z), "f"(v.w)
                         : "memory");
        }
    }
    if (tid < 128) {
        float gte = sgate[tid];
        int di = g_dst[e0 + tid];
        atomicAdd(&outx[di * 3 + 0], sgx[tid] * gte);
        atomicAdd(&outx[di * 3 + 1], sgy[tid] * gte);
        atomicAdd(&outx[di * 3 + 2], sgz[tid] * gte);
    }
}

// ---------------- node update: LN(h + phi_h([h,agg])) (tensor) --------------
__global__ __launch_bounds__(256, 1) void k_node_upd(
    const float* __restrict__ h, const float* __restrict__ Wh1,
    const float* __restrict__ bh1, const float* __restrict__ Wh2,
    const float* __restrict__ bh2, const float* __restrict__ lng,
    const float* __restrict__ lnb, float* __restrict__ outh) {
    extern __shared__ float sm[];
    float* ht = sm;              // 128*SP
    float* at = ht + 128 * SP;   // agg, later tt
    float* wt = at + 128 * SP;   // 128*SP
    float* bh1s = wt + 128 * SP;
    float* bh2s = bh1s + 128;
    float* lngs = bh2s + 128;
    float* lnbs = lngs + 128;
    float* ssum = lnbs + 128;
    float* ssq = ssum + 128;

    int tid = threadIdx.x, lane = tid & 31, warp = tid >> 5;
    int n0 = blockIdx.x * 128;

    if (tid < 128) {
        bh1s[tid] = bh1[tid];
        bh2s[tid] = bh2[tid];
        lngs[tid] = lng[tid];
        lnbs[tid] = lnb[tid];
        ssum[tid] = 0.f;
        ssq[tid] = 0.f;
    }
#pragma unroll
    for (int v = 0; v < 16; v++) {
        int f = v * 256 + tid;
        int r = f >> 5, c4 = (f & 31) * 4;
        float4 hv = make_float4(0.f, 0.f, 0.f, 0.f);
        float4 av = make_float4(0.f, 0.f, 0.f, 0.f);
        if (n0 + r < NN) {
            hv = *(const float4*)&h[(n0 + r) * 128 + c4];
            av = *(const float4*)&g_agg[(n0 + r) * 128 + c4];
        }
        *(float4*)&ht[r * SP + c4] = hv;
        *(float4*)&at[r * SP + c4] = av;
    }
    stage_wt(wt, Wh1, tid);
    __syncthreads();

    int mrow = (warp >> 1) * 32, ncol = (warp & 1) * 64;
    int g = lane >> 2, tg = lane & 3;

    // GEMM1: [h|agg] @ Wh1 + bh1 (K=256 in two passes)
    float acc[2][8][4];
    acc_init_bias(acc, bh1s, ncol, tg);
    gemm_kloop(ht, wt, mrow, ncol, lane, acc);
    __syncthreads();
    stage_wt(wt, Wh1 + 128 * 128, tid);
    __syncthreads();
    gemm_kloop(at, wt, mrow, ncol, lane, acc);
    __syncthreads();  // all warps done reading agg tile

    // tt = silu(acc) -> at buffer
#pragma unroll
    for (int mt = 0; mt < 2; mt++)
#pragma unroll
        for (int nt = 0; nt < 8; nt++) {
            int r = mrow + mt * 16 + g;
            int cb = ncol + nt * 8 + tg * 2;
            *(float2*)&at[r * SP + cb] =
                make_float2(siluf(acc[mt][nt][0]), siluf(acc[mt][nt][1]));
            *(float2*)&at[(r + 8) * SP + cb] =
                make_float2(siluf(acc[mt][nt][2]), siluf(acc[mt][nt][3]));
        }
    __syncthreads();
    stage_wt(wt, Wh2, tid);
    __syncthreads();

    // GEMM2: dh = tt @ Wh2 + bh2 ; v = h + dh
    float acc2[2][8][4];
    acc_init_bias(acc2, bh2s, ncol, tg);
    gemm_kloop(at, wt, mrow, ncol, lane, acc2);

    float vsum[4] = {0.f, 0.f, 0.f, 0.f};
    float vsq[4] = {0.f, 0.f, 0.f, 0.f};
#pragma unroll
    for (int mt = 0; mt < 2; mt++)
#pragma unroll
        for (int nt = 0; nt < 8; nt++) {
            int r = mrow + mt * 16 + g;
            int cb = ncol + nt * 8 + tg * 2;
            float v0 = ht[r * SP + cb] + acc2[mt][nt][0];
            float v1 = ht[r * SP + cb + 1] + acc2[mt][nt][1];
            float v2 = ht[(r + 8) * SP + cb] + acc2[mt][nt][2];
            float v3 = ht[(r + 8) * SP + cb + 1] + acc2[mt][nt][3];
            acc2[mt][nt][0] = v0; acc2[mt][nt][1] = v1;
            acc2[mt][nt][2] = v2; acc2[mt][nt][3] = v3;
            vsum[mt * 2 + 0] += v0 + v1;
            vsq[mt * 2 + 0] += v0 * v0 + v1 * v1;
            vsum[mt * 2 + 1] += v2 + v3;
            vsq[mt * 2 + 1] += v2 * v2 + v3 * v3;
        }
#pragma unroll
    for (int i = 0; i < 4; i++) {
        vsum[i] += __shfl_xor_sync(0xffffffffu, vsum[i], 1);
        vsum[i] += __shfl_xor_sync(0xffffffffu, vsum[i], 2);
        vsq[i] += __shfl_xor_sync(0xffffffffu, vsq[i], 1);
        vsq[i] += __shfl_xor_sync(0xffffffffu, vsq[i], 2);
    }
    {
        float sv = (tg == 0) ? vsum[0] : (tg == 1) ? vsum[1] : (tg == 2) ? vsum[2] : vsum[3];
        float qv = (tg == 0) ? vsq[0] : (tg == 1) ? vsq[1] : (tg == 2) ? vsq[2] : vsq[3];
        int row = mrow + tg * 8 + g;
        atomicAdd(&ssum[row], sv);
        atomicAdd(&ssq[row], qv);
    }
    __syncthreads();

#pragma unroll
    for (int mt = 0; mt < 2; mt++)
#pragma unroll
        for (int nt = 0; nt < 8; nt++) {
            int r = mrow + mt * 16 + g;
            int cb = ncol + nt * 8 + tg * 2;
            float mean0 = ssum[r] * (1.0f / 128.0f);
            float var0 = ssq[r] * (1.0f / 128.0f) - mean0 * mean0;
            float rstd0 = rsqrtf(var0 + 1e-5f);
            float mean1 = ssum[r + 8] * (1.0f / 128.0f);
            float var1 = ssq[r + 8] * (1.0f / 128.0f) - mean1 * mean1;
            float rstd1 = rsqrtf(var1 + 1e-5f);
            float g0 = lngs[cb], g1 = lngs[cb + 1];
            float b0 = lnbs[cb], b1 = lnbs[cb + 1];
            if (n0 + r < NN)
                *(float2*)&outh[(n0 + r) * 128 + cb] = make_float2(
                    (acc2[mt][nt][0] - mean0) * rstd0 * g0 + b0,
                    (acc2[mt][nt][1] - mean0) * rstd0 * g1 + b1);
            if (n0 + r + 8 < NN)
                *(float2*)&outh[(n0 + r + 8) * 128 + cb] = make_float2(
                    (acc2[mt][nt][2] - mean1) * rstd1 * g0 + b0,
                    (acc2[mt][nt][3] - mean1) * rstd1 * g1 + b1);
        }
}

// ---------------- launcher ---------------------------------------------------
extern "C" void kernel_launch(void* const* d_in, const int* in_sizes, int n_in,
                              void* d_out, int out_size) {
    const float* h = (const float*)d_in[0];
    const float* x = (const float*)d_in[1];
    const void* ei = d_in[2];
    const float* ea = (const float*)d_in[3];
    const float* We1 = (const float*)d_in[4];
    const float* be1 = (const float*)d_in[5];
    const float* We2 = (const float*)d_in[6];
    const float* be2 = (const float*)d_in[7];
    const float* Wh1 = (const float*)d_in[8];
    const float* bh1 = (const float*)d_in[9];
    const float* Wh2 = (const float*)d_in[10];
    const float* bh2 = (const float*)d_in[11];
    const float* Wx1 = (const float*)d_in[12];
    const float* bx1 = (const float*)d_in[13];
    const float* Wx2 = (const float*)d_in[14];
    const float* bx2 = (const float*)d_in[15];
    const float* lng = (const float*)d_in[16];
    const float* lnb = (const float*)d_in[17];

    float* outh = (float*)d_out;
    float* outx = outh + (size_t)NN * HH;

    const int SMEM_EDGE = (3 * 128 * SP + 16 * SP + 5 * 128 + 4 * 128) * 4;  // 215808
    const int SMEM_PRE = (2 * 128 * SP) * 4;                                  // 135168
    const int SMEM_UPD = (3 * 128 * SP + 6 * 128) * 4;                        // 205824
    cudaFuncSetAttribute(k_edge, cudaFuncAttributeMaxDynamicSharedMemorySize, SMEM_EDGE);
    cudaFuncSetAttribute(k_node_pre, cudaFuncAttributeMaxDynamicSharedMemorySize, SMEM_PRE);
    cudaFuncSetAttribute(k_node_upd, cudaFuncAttributeMaxDynamicSharedMemorySize, SMEM_UPD);

    k_detect<<<1, 32>>>(ei);
    k_convert<<<(EE + 255) / 256, 256>>>(ei);
    k_init<<<1024, 256>>>(x, outx);
    k_node_pre<<<(NN + 127) / 128, 256, SMEM_PRE>>>(h, We1);
    k_edge<<<EE / 128, 256, SMEM_EDGE>>>(x, ea, We1, be1, We2, be2, Wx1, bx1, Wx2,
                                         bx2, outx);
    k_node_upd<<<(NN + 127) / 128, 256, SMEM_UPD>>>(h, Wh1, bh1, Wh2, bh2, lng, lnb,
                                                    outh);
}

// round 5
// speedup vs baseline: 3.8551x; 1.1290x over previous
#include <cuda_runtime.h>

#define NN 50000
#define EE 800000
#define SP 132
#define EAP 26
#define NTILE_E (EE / 128)
#define NTILE_N ((NN + 127) / 128)
#define PGRID 148

// ---------------- scratch (device globals) ----------------------------------
__device__ int   g_is64;
__device__ int   g_src[EE];
__device__ int   g_dst[EE];
__device__ float g_A[NN * 128];    // h @ We1[0:128]
__device__ float g_B[NN * 128];    // h @ We1[128:256]
__device__ float g_agg[NN * 128];  // segment-sum of m

__device__ __forceinline__ float siluf(float v) {
    return __fdividef(v, 1.0f + __expf(-v));
}

__device__ __forceinline__ unsigned f2tf(float v) {
    unsigned u;
    asm("cvt.rna.tf32.f32 %0, %1;" : "=r"(u) : "f"(v));
    return u;
}

__device__ __forceinline__ void mma8(float* c, const unsigned* a, const unsigned* b) {
    asm volatile(
        "mma.sync.aligned.m16n8k8.row.col.f32.tf32.tf32.f32 "
        "{%0,%1,%2,%3},{%4,%5,%6,%7},{%8,%9},{%0,%1,%2,%3};"
        : "+f"(c[0]), "+f"(c[1]), "+f"(c[2]), "+f"(c[3])
        : "r"(a[0]), "r"(a[1]), "r"(a[2]), "r"(a[3]), "r"(b[0]), "r"(b[1]));
}

// ---- weight staging: W row-major K=128 x N=128 -> WT[n][k] tf32, pad SP ----
__device__ __forceinline__ void stage_wt512(float* wt, const float* __restrict__ W,
                                            int tid) {
    int lane = tid & 31, warp = tid >> 5;
    int n = (lane & 7) + 8 * warp;
    int k_l = lane >> 3;
#pragma unroll 4
    for (int q = 0; q < 32; q++) {
        int k = k_l + 4 * q;
        wt[n * SP + k] = __uint_as_float(f2tf(W[k * 128 + n]));
    }
}

__device__ __forceinline__ void stage_wt256(float* wt, const float* __restrict__ W,
                                            int tid) {
    int lane = tid & 31, warp = tid >> 5;
    int n_lo = lane & 7, k_l = lane >> 3;
#pragma unroll
    for (int p = 0; p < 2; p++) {
        int n = n_lo + 8 * (2 * warp + p);
#pragma unroll 4
        for (int q = 0; q < 32; q++) {
            int k = k_l + 4 * q;
            wt[n * SP + k] = __uint_as_float(f2tf(W[k * 128 + n]));
        }
    }
}

// ---- M=16 warp-tile K=128 k-loop (16-warp kernels) -------------------------
__device__ __forceinline__ void gemm_kloop16(const float* sA, const float* wt,
                                             int mrow, int ncol, int lane,
                                             float acc[8][4]) {
    int g = lane >> 2, tg = lane & 3;
    const float* a0p = sA + (mrow + g) * SP + tg;
    const float* b0p = wt + (ncol + g) * SP + tg;
#pragma unroll 4
    for (int kk = 0; kk < 16; kk++) {
        int k0 = kk * 8;
        unsigned a[4];
        const float* ap = a0p + k0;
        a[0] = f2tf(ap[0]);
        a[1] = f2tf(ap[8 * SP]);
        a[2] = f2tf(ap[4]);
        a[3] = f2tf(ap[8 * SP + 4]);
#pragma unroll
        for (int nt = 0; nt < 8; nt++) {
            const float* bp = b0p + nt * 8 * SP + k0;
            unsigned b[2] = {__float_as_uint(bp[0]), __float_as_uint(bp[4])};
            mma8(acc[nt], a, b);
        }
    }
}

__device__ __forceinline__ void acc_init_bias16(float acc[8][4], const float* bias,
                                                int ncol, int tg) {
#pragma unroll
    for (int nt = 0; nt < 8; nt++) {
        int cb = ncol + nt * 8 + tg * 2;
        float b0v = bias[cb], b1v = bias[cb + 1];
        acc[nt][0] = b0v;
        acc[nt][1] = b1v;
        acc[nt][2] = b0v;
        acc[nt][3] = b1v;
    }
}

// ---- M=32 warp-tile (node_upd 256-thread kernel) ---------------------------
__device__ __forceinline__ void gemm_kloop(const float* sA, const float* wt,
                                           int mrow, int ncol, int lane,
                                           float acc[2][8][4]) {
    int g = lane >> 2, tg = lane & 3;
    const float* a0p = sA + (mrow + g) * SP + tg;
    const float* b0p = wt + (ncol + g) * SP + tg;
#pragma unroll 4
    for (int kk = 0; kk < 16; kk++) {
        int k0 = kk * 8;
        unsigned a[2][4];
#pragma unroll
        for (int mt = 0; mt < 2; mt++) {
            const float* ap = a0p + mt * 16 * SP + k0;
            a[mt][0] = f2tf(ap[0]);
            a[mt][1] = f2tf(ap[8 * SP]);
            a[mt][2] = f2tf(ap[4]);
            a[mt][3] = f2tf(ap[8 * SP + 4]);
        }
#pragma unroll
        for (int nt = 0; nt < 8; nt++) {
            const float* bp = b0p + nt * 8 * SP + k0;
            unsigned b[2];
            b[0] = __float_as_uint(bp[0]);
            b[1] = __float_as_uint(bp[4]);
            mma8(acc[0][nt], a[0], b);
            mma8(acc[1][nt], a[1], b);
        }
    }
}

__device__ __forceinline__ void acc_init_bias(float acc[2][8][4], const float* bias,
                                              int ncol, int tg) {
#pragma unroll
    for (int nt = 0; nt < 8; nt++) {
        int cb = ncol + nt * 8 + tg * 2;
        float b0v = bias[cb], b1v = bias[cb + 1];
#pragma unroll
        for (int mt = 0; mt < 2; mt++) {
            acc[mt][nt][0] = b0v;
            acc[mt][nt][1] = b1v;
            acc[mt][nt][2] = b0v;
            acc[mt][nt][3] = b1v;
        }
    }
}

// ---------------- index dtype detection + conversion ------------------------
__global__ void k_detect(const void* ei) {
    if (blockIdx.x == 0 && threadIdx.x == 0) {
        const int* p = (const int*)ei;
        int acc = 0;
        for (int i = 0; i < 64; i++) acc |= p[2 * i + 1];
        g_is64 = (acc == 0) ? 1 : 0;
    }
}

__global__ void k_convert(const void* ei) {
    int e = blockIdx.x * blockDim.x + threadIdx.x;
    if (e >= EE) return;
    if (g_is64) {
        const long long* p = (const long long*)ei;
        g_src[e] = (int)p[e];
        g_dst[e] = (int)p[EE + e];
    } else {
        const int* p = (const int*)ei;
        g_src[e] = p[e];
        g_dst[e] = p[EE + e];
    }
}

// ---------------- init: zero agg, x_out = x ---------------------------------
__global__ void k_init(const float* __restrict__ x, float* __restrict__ outx) {
    for (int i = blockIdx.x * blockDim.x + threadIdx.x; i < NN * 128;
         i += gridDim.x * blockDim.x) {
        g_agg[i] = 0.0f;
        if (i < NN * 3) outx[i] = x[i];
    }
}

// ---------------- node pre-GEMM (persistent): A = h@We1a, B = h@We1b --------
__global__ __launch_bounds__(512, 1) void k_node_pre(
    const float* __restrict__ h, const float* __restrict__ We1) {
    extern __shared__ float sm[];
    float* ht = sm;               // 128*SP
    float* wtA = ht + 128 * SP;   // 128*SP
    float* wtB = wtA + 128 * SP;  // 128*SP

    int tid = threadIdx.x, lane = tid & 31, warp = tid >> 5;
    stage_wt512(wtA, We1, tid);
    stage_wt512(wtB, We1 + 128 * 128, tid);
    __syncthreads();

    int mrow = (warp >> 1) * 16, ncol = (warp & 1) * 64;
    int g = lane >> 2, tg = lane & 3;

    for (int t = blockIdx.x; t < NTILE_N; t += gridDim.x) {
        int n0 = t * 128;
#pragma unroll
        for (int v = 0; v < 8; v++) {
            int f = v * 512 + tid;
            int r = f >> 5, c4 = (f & 31) * 4;
            float4 val = make_float4(0.f, 0.f, 0.f, 0.f);
            if (n0 + r < NN) val = *(const float4*)&h[(n0 + r) * 128 + c4];
            *(float4*)&ht[r * SP + c4] = val;
        }
        __syncthreads();
#pragma unroll
        for (int half = 0; half < 2; half++) {
            float acc[8][4];
#pragma unroll
            for (int nt = 0; nt < 8; nt++)
#pragma unroll
                for (int l = 0; l < 4; l++) acc[nt][l] = 0.f;
            gemm_kloop16(ht, half ? wtB : wtA, mrow, ncol, lane, acc);
            float* out = half ? g_B : g_A;
#pragma unroll
            for (int nt = 0; nt < 8; nt++) {
                int r = mrow + g;
                int cb = ncol + nt * 8 + tg * 2;
                if (n0 + r < NN)
                    *(float2*)&out[(n0 + r) * 128 + cb] = make_float2(acc[nt][0], acc[nt][1]);
                if (n0 + r + 8 < NN)
                    *(float2*)&out[(n0 + r + 8) * 128 + cb] = make_float2(acc[nt][2], acc[nt][3]);
            }
        }
        __syncthreads();
    }
}

// ---------------- fused edge kernel (persistent, resident weights) ----------
__global__ __launch_bounds__(512, 1) void k_edge(
    const float* __restrict__ x, const float* __restrict__ ea,
    const float* __restrict__ We1, const float* __restrict__ be1,
    const float* __restrict__ We2, const float* __restrict__ be2,
    const float* __restrict__ Wx1, const float* __restrict__ bx1,
    const float* __restrict__ Wx2, const float* __restrict__ bx2,
    float* __restrict__ outx) {
    extern __shared__ float sm[];
    float* tile = sm;                   // 128*SP (pre -> s -> mm)
    float* wt2 = tile + 128 * SP;       // We2^T
    float* wtx = wt2 + 128 * SP;        // Wx1^T
    float* sEA = wtx + 128 * SP;        // 128*EAP  [ea(16)|dist|1|pad|src,dst]
    float* wtE = sEA + 128 * EAP;       // 128*EAP  [We1e|wd|be1]^T
    float* be2s = wtE + 128 * EAP;
    float* bx1s = be2s + 128;
    float* wx2s = bx1s + 128;
    float* sgate = wx2s + 128;

    int tid = threadIdx.x, lane = tid & 31, warp = tid >> 5;

    // ---- one-time staging ----
    stage_wt512(wt2, We2, tid);
    stage_wt512(wtx, Wx1, tid);
    for (int idx = tid; idx < 128 * EAP; idx += 512) {
        int n = idx / EAP, k = idx % EAP;
        float v = 0.f;
        if (k < 16) v = We1[(256 + k) * 128 + n];
        else if (k == 16) v = We1[272 * 128 + n];
        else if (k == 17) v = be1[n];
        wtE[idx] = __uint_as_float(f2tf(v));
    }
    for (int r = tid; r < 128; r += 512)
#pragma unroll
        for (int k = 18; k < 24; k++) sEA[r * EAP + k] = 0.f;
    if (tid < 128) {
        be2s[tid] = be2[tid];
        bx1s[tid] = bx1[tid];
        wx2s[tid] = Wx2[tid];
    }
    float bx2v = bx2[0];
    __syncthreads();

    int mrow = (warp >> 1) * 16, ncol = (warp & 1) * 64;
    int g = lane >> 2, tg = lane & 3;
    int e_l = tid >> 2, q = tid & 3;

    for (int t = blockIdx.x; t < NTILE_E; t += gridDim.x) {
        int e0 = t * 128;

        // ---- stage edge tile ----
        {
            int e = e0 + e_l;
            float4 t4 = *(const float4*)&ea[e * 16 + q * 4];
            // EAP=26 rows are only 8B-aligned -> use float2 stores (not float4)
            *(float2*)&sEA[e_l * EAP + q * 4] = make_float2(t4.x, t4.y);
            *(float2*)&sEA[e_l * EAP + q * 4 + 2] = make_float2(t4.z, t4.w);
            if (q == 0) {
                int si = g_src[e], di = g_dst[e];
                float dx = x[di * 3 + 0] - x[si * 3 + 0];
                float dy = x[di * 3 + 1] - x[si * 3 + 1];
                float dz = x[di * 3 + 2] - x[si * 3 + 2];
                float ss2 = dx * dx + dy * dy + dz * dz;
                sEA[e_l * EAP + 16] = sqrtf(ss2 + 1e-9f);
                sEA[e_l * EAP + 17] = 1.0f;
                ((int*)sEA)[e_l * EAP + 24] = si;
                ((int*)sEA)[e_l * EAP + 25] = di;
            }
            if (tid < 128) sgate[tid] = bx2v;
        }
        __syncthreads();

        // ---- GEMM_ea (K=24): pre = [ea|dist|1] @ [We1e;wd;be1] -> tile ----
        {
            float acc[8][4];
#pragma unroll
            for (int nt = 0; nt < 8; nt++)
#pragma unroll
                for (int l = 0; l < 4; l++) acc[nt][l] = 0.f;
            const float* a0p = sEA + (mrow + g) * EAP + tg;
            const float* b0p = wtE + (ncol + g) * EAP + tg;
#pragma unroll
            for (int kk = 0; kk < 3; kk++) {
                int k0 = kk * 8;
                unsigned a[4];
                a[0] = f2tf(a0p[k0]);
                a[1] = f2tf(a0p[8 * EAP + k0]);
                a[2] = f2tf(a0p[k0 + 4]);
                a[3] = f2tf(a0p[8 * EAP + k0 + 4]);
#pragma unroll
                for (int nt = 0; nt < 8; nt++) {
                    const float* bp = b0p + nt * 8 * EAP + k0;
                    unsigned b[2] = {__float_as_uint(bp[0]), __float_as_uint(bp[4])};
                    mma8(acc[nt], a, b);
                }
            }
#pragma unroll
            for (int nt = 0; nt < 8; nt++) {
                int r = mrow + g;
                int cb = ncol + nt * 8 + tg * 2;
                *(float2*)&tile[r * SP + cb] = make_float2(acc[nt][0], acc[nt][1]);
                *(float2*)&tile[(r + 8) * SP + cb] = make_float2(acc[nt][2], acc[nt][3]);
            }
        }
        __syncthreads();

        // ---- phase1b: s = silu(pre + A[src] + B[dst]) in place ----
        {
            int si = ((const int*)sEA)[e_l * EAP + 24];
            int di = ((const int*)sEA)[e_l * EAP + 25];
            const float4* A4 = (const float4*)g_A + si * 32 + q * 8;
            const float4* B4 = (const float4*)g_B + di * 32 + q * 8;
            float* tp = &tile[e_l * SP + q * 32];
#pragma unroll
            for (int i = 0; i < 8; i++) {
                float4 a = A4[i], b = B4[i];
                float4 tv = *(float4*)&tp[i * 4];
                tv.x = siluf(tv.x + a.x + b.x);
                tv.y = siluf(tv.y + a.y + b.y);
                tv.z = siluf(tv.z + a.z + b.z);
                tv.w = siluf(tv.w + a.w + b.w);
                *(float4*)&tp[i * 4] = tv;
            }
        }
        __syncthreads();

        // ---- GEMM1: mm = s @ We2 + be2 (acc in regs across overwrite) ----
        float accm[8][4];
        acc_init_bias16(accm, be2s, ncol, tg);
        gemm_kloop16(tile, wt2, mrow, ncol, lane, accm);
        __syncthreads();
#pragma unroll
        for (int nt = 0; nt < 8; nt++) {
            int r = mrow + g;
            int cb = ncol + nt * 8 + tg * 2;
            *(float2*)&tile[r * SP + cb] = make_float2(accm[nt][0], accm[nt][1]);
            *(float2*)&tile[(r + 8) * SP + cb] = make_float2(accm[nt][2], accm[nt][3]);
        }
        __syncthreads();

        // ---- GEMM2: gate = sum silu(mm@Wx1+bx1)*wx2 ----
        {
            float acc[8][4];
            acc_init_bias16(acc, bx1s, ncol, tg);
            gemm_kloop16(tile, wtx, mrow, ncol, lane, acc);
            float p0 = 0.f, p1 = 0.f;
#pragma unroll
            for (int nt = 0; nt < 8; nt++) {
                int cb = ncol + nt * 8 + tg * 2;
                float w0 = wx2s[cb], w1 = wx2s[cb + 1];
                p0 += siluf(acc[nt][0]) * w0 + siluf(acc[nt][1]) * w1;
                p1 += siluf(acc[nt][2]) * w0 + siluf(acc[nt][3]) * w1;
            }
            p0 += __shfl_xor_sync(0xffffffffu, p0, 1);
            p0 += __shfl_xor_sync(0xffffffffu, p0, 2);
            p1 += __shfl_xor_sync(0xffffffffu, p1, 1);
            p1 += __shfl_xor_sync(0xffffffffu, p1, 2);
            if (tg == 0) {
                atomicAdd(&sgate[mrow + g], p0);
                atomicAdd(&sgate[mrow + g + 8], p1);
            }
        }
        __syncthreads();

        // ---- scatter: agg[dst] += m ; x_out[dst] += dir*gate ----
        {
            int di = ((const int*)sEA)[e_l * EAP + 25];
            float* dstp = &g_agg[di * 128 + q * 32];
            const float* mp = &tile[e_l * SP + q * 32];
#pragma unroll
            for (int i = 0; i < 8; i++) {
                float4 v = *(const float4*)&mp[i * 4];
                asm volatile("red.global.add.v4.f32 [%0], {%1,%2,%3,%4};"
                             :: "l"(dstp + i * 4), "f"(v.x), "f"(v.y), "f"(v.z), "f"(v.w)
                             : "memory");
            }
        }
        if (tid < 128) {
            int si = ((const int*)sEA)[tid * EAP + 24];
            int di = ((const int*)sEA)[tid * EAP + 25];
            float dx = x[di * 3 + 0] - x[si * 3 + 0];
            float dy = x[di * 3 + 1] - x[si * 3 + 1];
            float dz = x[di * 3 + 2] - x[si * 3 + 2];
            float rn = __fdividef(1.0f, sqrtf(dx * dx + dy * dy + dz * dz) + 1e-9f);
            float gte = sgate[tid];
            atomicAdd(&outx[di * 3 + 0], dx * rn * gte);
            atomicAdd(&outx[di * 3 + 1], dy * rn * gte);
            atomicAdd(&outx[di * 3 + 2], dz * rn * gte);
        }
        __syncthreads();
    }
}

// ---------------- node update: LN(h + phi_h([h,agg])) (tensor) --------------
__global__ __launch_bounds__(256, 1) void k_node_upd(
    const float* __restrict__ h, const float* __restrict__ Wh1,
    const float* __restrict__ bh1, const float* __restrict__ Wh2,
    const float* __restrict__ bh2, const float* __restrict__ lng,
    const float* __restrict__ lnb, float* __restrict__ outh) {
    extern __shared__ float sm[];
    float* ht = sm;              // 128*SP
    float* at = ht + 128 * SP;   // agg, later tt
    float* wt = at + 128 * SP;   // 128*SP
    float* bh1s = wt + 128 * SP;
    float* bh2s = bh1s + 128;
    float* lngs = bh2s + 128;
    float* lnbs = lngs + 128;
    float* ssum = lnbs + 128;
    float* ssq = ssum + 128;

    int tid = threadIdx.x, lane = tid & 31, warp = tid >> 5;
    int n0 = blockIdx.x * 128;

    if (tid < 128) {
        bh1s[tid] = bh1[tid];
        bh2s[tid] = bh2[tid];
        lngs[tid] = lng[tid];
        lnbs[tid] = lnb[tid];
        ssum[tid] = 0.f;
        ssq[tid] = 0.f;
    }
#pragma unroll
    for (int v = 0; v < 16; v++) {
        int f = v * 256 + tid;
        int r = f >> 5, c4 = (f & 31) * 4;
        float4 hv = make_float4(0.f, 0.f, 0.f, 0.f);
        float4 av = make_float4(0.f, 0.f, 0.f, 0.f);
        if (n0 + r < NN) {
            hv = *(const float4*)&h[(n0 + r) * 128 + c4];
            av = *(const float4*)&g_agg[(n0 + r) * 128 + c4];
        }
        *(float4*)&ht[r * SP + c4] = hv;
        *(float4*)&at[r * SP + c4] = av;
    }
    stage_wt256(wt, Wh1, tid);
    __syncthreads();

    int mrow = (warp >> 1) * 32, ncol = (warp & 1) * 64;
    int g = lane >> 2, tg = lane & 3;

    float acc[2][8][4];
    acc_init_bias(acc, bh1s, ncol, tg);
    gemm_kloop(ht, wt, mrow, ncol, lane, acc);
    __syncthreads();
    stage_wt256(wt, Wh1 + 128 * 128, tid);
    __syncthreads();
    gemm_kloop(at, wt, mrow, ncol, lane, acc);
    __syncthreads();

#pragma unroll
    for (int mt = 0; mt < 2; mt++)
#pragma unroll
        for (int nt = 0; nt < 8; nt++) {
            int r = mrow + mt * 16 + g;
            int cb = ncol + nt * 8 + tg * 2;
            *(float2*)&at[r * SP + cb] =
                make_float2(siluf(acc[mt][nt][0]), siluf(acc[mt][nt][1]));
            *(float2*)&at[(r + 8) * SP + cb] =
                make_float2(siluf(acc[mt][nt][2]), siluf(acc[mt][nt][3]));
        }
    __syncthreads();
    stage_wt256(wt, Wh2, tid);
    __syncthreads();

    float acc2[2][8][4];
    acc_init_bias(acc2, bh2s, ncol, tg);
    gemm_kloop(at, wt, mrow, ncol, lane, acc2);

    float vsum[4] = {0.f, 0.f, 0.f, 0.f};
    float vsq[4] = {0.f, 0.f, 0.f, 0.f};
#pragma unroll
    for (int mt = 0; mt < 2; mt++)
#pragma unroll
        for (int nt = 0; nt < 8; nt++) {
            int r = mrow + mt * 16 + g;
            int cb = ncol + nt * 8 + tg * 2;
            float v0 = ht[r * SP + cb] + acc2[mt][nt][0];
            float v1 = ht[r * SP + cb + 1] + acc2[mt][nt][1];
            float v2 = ht[(r + 8) * SP + cb] + acc2[mt][nt][2];
            float v3 = ht[(r + 8) * SP + cb + 1] + acc2[mt][nt][3];
            acc2[mt][nt][0] = v0; acc2[mt][nt][1] = v1;
            acc2[mt][nt][2] = v2; acc2[mt][nt][3] = v3;
            vsum[mt * 2 + 0] += v0 + v1;
            vsq[mt * 2 + 0] += v0 * v0 + v1 * v1;
            vsum[mt * 2 + 1] += v2 + v3;
            vsq[mt * 2 + 1] += v2 * v2 + v3 * v3;
        }
#pragma unroll
    for (int i = 0; i < 4; i++) {
        vsum[i] += __shfl_xor_sync(0xffffffffu, vsum[i], 1);
        vsum[i] += __shfl_xor_sync(0xffffffffu, vsum[i], 2);
        vsq[i] += __shfl_xor_sync(0xffffffffu, vsq[i], 1);
        vsq[i] += __shfl_xor_sync(0xffffffffu, vsq[i], 2);
    }
    {
        float sv = (tg == 0) ? vsum[0] : (tg == 1) ? vsum[1] : (tg == 2) ? vsum[2] : vsum[3];
        float qv = (tg == 0) ? vsq[0] : (tg == 1) ? vsq[1] : (tg == 2) ? vsq[2] : vsq[3];
        int row = mrow + tg * 8 + g;
        atomicAdd(&ssum[row], sv);
        atomicAdd(&ssq[row], qv);
    }
    __syncthreads();

#pragma unroll
    for (int mt = 0; mt < 2; mt++)
#pragma unroll
        for (int nt = 0; nt < 8; nt++) {
            int r = mrow + mt * 16 + g;
            int cb = ncol + nt * 8 + tg * 2;
            float mean0 = ssum[r] * (1.0f / 128.0f);
            float var0 = ssq[r] * (1.0f / 128.0f) - mean0 * mean0;
            float rstd0 = rsqrtf(var0 + 1e-5f);
            float mean1 = ssum[r + 8] * (1.0f / 128.0f);
            float var1 = ssq[r + 8] * (1.0f / 128.0f) - mean1 * mean1;
            float rstd1 = rsqrtf(var1 + 1e-5f);
            float g0 = lngs[cb], g1 = lngs[cb + 1];
            float b0 = lnbs[cb], b1 = lnbs[cb + 1];
            if (n0 + r < NN)
                *(float2*)&outh[(n0 + r) * 128 + cb] = make_float2(
                    (acc2[mt][nt][0] - mean0) * rstd0 * g0 + b0,
                    (acc2[mt][nt][1] - mean0) * rstd0 * g1 + b1);
            if (n0 + r + 8 < NN)
                *(float2*)&outh[(n0 + r + 8) * 128 + cb] = make_float2(
                    (acc2[mt][nt][2] - mean1) * rstd1 * g0 + b0,
                    (acc2[mt][nt][3] - mean1) * rstd1 * g1 + b1);
        }
}

// ---------------- launcher ---------------------------------------------------
extern "C" void kernel_launch(void* const* d_in, const int* in_sizes, int n_in,
                              void* d_out, int out_size) {
    const float* h = (const float*)d_in[0];
    const float* x = (const float*)d_in[1];
    const void* ei = d_in[2];
    const float* ea = (const float*)d_in[3];
    const float* We1 = (const float*)d_in[4];
    const float* be1 = (const float*)d_in[5];
    const float* We2 = (const float*)d_in[6];
    const float* be2 = (const float*)d_in[7];
    const float* Wh1 = (const float*)d_in[8];
    const float* bh1 = (const float*)d_in[9];
    const float* Wh2 = (const float*)d_in[10];
    const float* bh2 = (const float*)d_in[11];
    const float* Wx1 = (const float*)d_in[12];
    const float* bx1 = (const float*)d_in[13];
    const float* Wx2 = (const float*)d_in[14];
    const float* bx2 = (const float*)d_in[15];
    const float* lng = (const float*)d_in[16];
    const float* lnb = (const float*)d_in[17];

    float* outh = (float*)d_out;
    float* outx = outh + (size_t)NN * 128;

    const int SMEM_EDGE = (3 * 128 * SP + 2 * 128 * EAP + 4 * 128) * 4;  // 231424
    const int SMEM_PRE = (3 * 128 * SP) * 4;                              // 202752
    const int SMEM_UPD = (3 * 128 * SP + 6 * 128) * 4;                    // 205824
    cudaFuncSetAttribute(k_edge, cudaFuncAttributeMaxDynamicSharedMemorySize, SMEM_EDGE);
    cudaFuncSetAttribute(k_node_pre, cudaFuncAttributeMaxDynamicSharedMemorySize, SMEM_PRE);
    cudaFuncSetAttribute(k_node_upd, cudaFuncAttributeMaxDynamicSharedMemorySize, SMEM_UPD);

    k_detect<<<1, 32>>>(ei);
    k_convert<<<(EE + 255) / 256, 256>>>(ei);
    k_init<<<1024, 256>>>(x, outx);
    k_node_pre<<<PGRID, 512, SMEM_PRE>>>(h, We1);
    k_edge<<<PGRID, 512, SMEM_EDGE>>>(x, ea, We1, be1, We2, be2, Wx1, bx1, Wx2,
                                      bx2, outx);
    k_node_upd<<<(NN + 127) / 128, 256, SMEM_UPD>>>(h, Wh1, bh1, Wh2, bh2, lng, lnb,
                                                    outh);
}

// round 6
// speedup vs baseline: 5.0248x; 1.3034x over previous
#include <cuda_runtime.h>

#define NN 50000
#define EE 800000
#define SP 136
#define NTILE_E (EE / 128)
#define NTILE_N ((NN + 127) / 128)
#define PGRID 148

// ---------------- scratch (device globals) ----------------------------------
__device__ int   g_is64;
__device__ int   g_src[EE];
__device__ int   g_dst[EE];
__device__ float g_A[NN * 128];    // h @ We1[0:128]
__device__ float g_B[NN * 128];    // h @ We1[128:256]
__device__ float g_agg[NN * 128];  // segment-sum of m

__device__ __forceinline__ float siluf(float v) {
    float t;
    asm("tanh.approx.f32 %0, %1;" : "=f"(t) : "f"(0.5f * v));
    return 0.5f * v * (1.0f + t);
}

__device__ __forceinline__ unsigned f2tf(float v) {
    unsigned u;
    asm("cvt.rna.tf32.f32 %0, %1;" : "=r"(u) : "f"(v));
    return u;
}

// permuted position of k within its 8-group: slot(2t)=k0+t, slot(2t+1)=k0+t+4
__device__ __forceinline__ int kpos(int k) {
    return (k & ~7) + ((k & 3) * 2 + ((k >> 2) & 1));
}

__device__ __forceinline__ void mma8(float* c, const unsigned* a, const unsigned* b) {
    asm volatile(
        "mma.sync.aligned.m16n8k8.row.col.f32.tf32.tf32.f32 "
        "{%0,%1,%2,%3},{%4,%5,%6,%7},{%8,%9},{%0,%1,%2,%3};"
        : "+f"(c[0]), "+f"(c[1]), "+f"(c[2]), "+f"(c[3])
        : "r"(a[0]), "r"(a[1]), "r"(a[2]), "r"(a[3]), "r"(b[0]), "r"(b[1]));
}

// ---- stage weight K=128 x N=128 row-major -> WT[n][kpos(k)] tf32 (1024 thr) -
__device__ __forceinline__ void stage_wtp(float* wt, const float* __restrict__ W,
                                          int tid) {
#pragma unroll
    for (int s = 0; s < 16; s++) {
        int i = s * 1024 + tid;
        int n = i & 127, k = i >> 7;
        wt[n * SP + kpos(k)] = __uint_as_float(f2tf(W[k * 128 + n]));
    }
}

// ---- permuted-tf32 k-loop: M=16, N=32 (4 n-tiles), K=128 -------------------
__device__ __forceinline__ void gemm_kloop16p(const float* sA, const float* wt,
                                              int mrow, int ncol, int lane,
                                              float acc[4][4]) {
    int g = lane >> 2, tg = lane & 3;
    const float* ap0 = sA + (mrow + g) * SP + 2 * tg;
    const float* ap1 = ap0 + 8 * SP;
    const float* bp0 = wt + (ncol + g) * SP + 2 * tg;
#pragma unroll
    for (int kk = 0; kk < 16; kk++) {
        int k0 = kk * 8;
        float2 a02 = *(const float2*)(ap0 + k0);  // (k0+tg, k0+tg+4) of row g
        float2 a13 = *(const float2*)(ap1 + k0);  // same of row g+8
        unsigned a[4] = {__float_as_uint(a02.x), __float_as_uint(a13.x),
                         __float_as_uint(a02.y), __float_as_uint(a13.y)};
#pragma unroll
        for (int nt = 0; nt < 4; nt++) {
            float2 b = *(const float2*)(bp0 + nt * 8 * SP + k0);
            unsigned bb[2] = {__float_as_uint(b.x), __float_as_uint(b.y)};
            mma8(acc[nt], a, bb);
        }
    }
}

// ---- legacy M=32 helpers (node_upd, 256 threads) ---------------------------
__device__ __forceinline__ void stage_wt256(float* wt, const float* __restrict__ W,
                                            int tid) {
    int lane = tid & 31, warp = tid >> 5;
    int n_lo = lane & 7, k_l = lane >> 3;
#pragma unroll
    for (int p = 0; p < 2; p++) {
        int n = n_lo + 8 * (2 * warp + p);
#pragma unroll 4
        for (int q = 0; q < 32; q++) {
            int k = k_l + 4 * q;
            wt[n * SP + k] = __uint_as_float(f2tf(W[k * 128 + n]));
        }
    }
}

__device__ __forceinline__ void gemm_kloop(const float* sA, const float* wt,
                                           int mrow, int ncol, int lane,
                                           float acc[2][8][4]) {
    int g = lane >> 2, tg = lane & 3;
    const float* a0p = sA + (mrow + g) * SP + tg;
    const float* b0p = wt + (ncol + g) * SP + tg;
#pragma unroll 4
    for (int kk = 0; kk < 16; kk++) {
        int k0 = kk * 8;
        unsigned a[2][4];
#pragma unroll
        for (int mt = 0; mt < 2; mt++) {
            const float* ap = a0p + mt * 16 * SP + k0;
            a[mt][0] = f2tf(ap[0]);
            a[mt][1] = f2tf(ap[8 * SP]);
            a[mt][2] = f2tf(ap[4]);
            a[mt][3] = f2tf(ap[8 * SP + 4]);
        }
#pragma unroll
        for (int nt = 0; nt < 8; nt++) {
            const float* bp = b0p + nt * 8 * SP + k0;
            unsigned b[2];
            b[0] = __float_as_uint(bp[0]);
            b[1] = __float_as_uint(bp[4]);
            mma8(acc[0][nt], a[0], b);
            mma8(acc[1][nt], a[1], b);
        }
    }
}

__device__ __forceinline__ void acc_init_bias(float acc[2][8][4], const float* bias,
                                              int ncol, int tg) {
#pragma unroll
    for (int nt = 0; nt < 8; nt++) {
        int cb = ncol + nt * 8 + tg * 2;
        float b0v = bias[cb], b1v = bias[cb + 1];
#pragma unroll
        for (int mt = 0; mt < 2; mt++) {
            acc[mt][nt][0] = b0v;
            acc[mt][nt][1] = b1v;
            acc[mt][nt][2] = b0v;
            acc[mt][nt][3] = b1v;
        }
    }
}

// ---------------- index dtype detection + conversion ------------------------
__global__ void k_detect(const void* ei) {
    if (blockIdx.x == 0 && threadIdx.x == 0) {
        const int* p = (const int*)ei;
        int acc = 0;
        for (int i = 0; i < 64; i++) acc |= p[2 * i + 1];
        g_is64 = (acc == 0) ? 1 : 0;
    }
}

__global__ void k_convert(const void* ei) {
    int e = blockIdx.x * blockDim.x + threadIdx.x;
    if (e >= EE) return;
    if (g_is64) {
        const long long* p = (const long long*)ei;
        g_src[e] = (int)p[e];
        g_dst[e] = (int)p[EE + e];
    } else {
        const int* p = (const int*)ei;
        g_src[e] = p[e];
        g_dst[e] = p[EE + e];
    }
}

// ---------------- init: zero agg, x_out = x ---------------------------------
__global__ void k_init(const float* __restrict__ x, float* __restrict__ outx) {
    for (int i = blockIdx.x * blockDim.x + threadIdx.x; i < NN * 128;
         i += gridDim.x * blockDim.x) {
        g_agg[i] = 0.0f;
        if (i < NN * 3) outx[i] = x[i];
    }
}

// ---------------- node pre-GEMM (persistent, 1024 thr) ----------------------
__global__ __launch_bounds__(1024, 1) void k_node_pre(
    const float* __restrict__ h, const float* __restrict__ We1) {
    extern __shared__ float sm[];
    float* ht = sm;               // 128*SP (permuted tf32)
    float* wtA = ht + 128 * SP;
    float* wtB = wtA + 128 * SP;

    int tid = threadIdx.x, lane = tid & 31, warp = tid >> 5;
    stage_wtp(wtA, We1, tid);
    stage_wtp(wtB, We1 + 128 * 128, tid);
    __syncthreads();

    int mrow = (warp >> 2) * 16, ncol = (warp & 3) * 32;
    int g = lane >> 2, tg = lane & 3;

    for (int t = blockIdx.x; t < NTILE_N; t += gridDim.x) {
        int n0 = t * 128;
#pragma unroll
        for (int v = 0; v < 4; v++) {
            int f = v * 1024 + tid;
            int r = f >> 5, c4 = (f & 31) * 4;
            float4 val = make_float4(0.f, 0.f, 0.f, 0.f);
            if (n0 + r < NN) val = *(const float4*)&h[(n0 + r) * 128 + c4];
            int base = r * SP + (c4 & ~7);
            int off = (c4 & 7) >> 2;  // 0 or 1
            ht[base + 0 * 2 + off] = __uint_as_float(f2tf(val.x));
            ht[base + 1 * 2 + off] = __uint_as_float(f2tf(val.y));
            ht[base + 2 * 2 + off] = __uint_as_float(f2tf(val.z));
            ht[base + 3 * 2 + off] = __uint_as_float(f2tf(val.w));
        }
        __syncthreads();
#pragma unroll
        for (int half = 0; half < 2; half++) {
            float acc[4][4];
#pragma unroll
            for (int nt = 0; nt < 4; nt++)
#pragma unroll
                for (int l = 0; l < 4; l++) acc[nt][l] = 0.f;
            gemm_kloop16p(ht, half ? wtB : wtA, mrow, ncol, lane, acc);
            float* out = half ? g_B : g_A;
#pragma unroll
            for (int nt = 0; nt < 4; nt++) {
                int r = mrow + g;
                int cb = ncol + nt * 8 + tg * 2;
                if (n0 + r < NN)
                    *(float2*)&out[(n0 + r) * 128 + cb] = make_float2(acc[nt][0], acc[nt][1]);
                if (n0 + r + 8 < NN)
                    *(float2*)&out[(n0 + r + 8) * 128 + cb] = make_float2(acc[nt][2], acc[nt][3]);
            }
        }
        __syncthreads();
    }
}

// ---------------- fused edge kernel (persistent, 1024 thr) ------------------
__global__ __launch_bounds__(1024, 1) void k_edge(
    const float* __restrict__ x, const float* __restrict__ ea,
    const float* __restrict__ We1, const float* __restrict__ be1,
    const float* __restrict__ We2, const float* __restrict__ be2,
    const float* __restrict__ Wx1, const float* __restrict__ bx1,
    const float* __restrict__ Wx2, const float* __restrict__ bx2,
    float* __restrict__ outx) {
    extern __shared__ float sm[];
    float* tile = sm;                   // 128*SP (s -> mm, permuted tf32)
    float* wt2 = tile + 128 * SP;       // We2^T perm
    float* wtx = wt2 + 128 * SP;        // Wx1^T perm
    float* sEA = wtx + 128 * SP;        // 128*20: ea[0:16)|dist|src|dst|pad
    float* wtE = sEA + 128 * 20;        // 128*16: We1 edge-attr block, perm
    float* wds = wtE + 128 * 16;        // 128
    float* be1s = wds + 128;
    float* be2s = be1s + 128;
    float* bx1s = be2s + 128;
    float* wx2s = bx1s + 128;
    float* sgate = wx2s + 128;

    int tid = threadIdx.x, lane = tid & 31, warp = tid >> 5;

    // ---- one-time staging ----
    stage_wtp(wt2, We2, tid);
    stage_wtp(wtx, Wx1, tid);
#pragma unroll
    for (int s = 0; s < 2; s++) {
        int i = s * 1024 + tid;
        int n = i & 127, k = i >> 7;  // k 0..15
        wtE[n * 16 + kpos(k)] = __uint_as_float(f2tf(We1[(256 + k) * 128 + n]));
    }
    if (tid < 128) {
        wds[tid] = We1[272 * 128 + tid];
        be1s[tid] = be1[tid];
        be2s[tid] = be2[tid];
        bx1s[tid] = bx1[tid];
        wx2s[tid] = Wx2[tid];
    }
    float bx2v = bx2[0];
    __syncthreads();

    int mrow = (warp >> 2) * 16, ncol = (warp & 3) * 32;
    int g = lane >> 2, tg = lane & 3;
    int e_l = tid >> 3, q = tid & 7;

    for (int t = blockIdx.x; t < NTILE_E; t += gridDim.x) {
        int e0 = t * 128;

        // ---- stage edge tile ----
        {
            int e = e0 + e_l;
            *(float2*)&sEA[e_l * 20 + q * 2] = *(const float2*)&ea[e * 16 + q * 2];
            if (q == 0) {
                int si = g_src[e], di = g_dst[e];
                float dx = x[di * 3 + 0] - x[si * 3 + 0];
                float dy = x[di * 3 + 1] - x[si * 3 + 1];
                float dz = x[di * 3 + 2] - x[si * 3 + 2];
                sEA[e_l * 20 + 16] = sqrtf(dx * dx + dy * dy + dz * dz + 1e-9f);
                ((int*)sEA)[e_l * 20 + 17] = si;
                ((int*)sEA)[e_l * 20 + 18] = di;
            }
            if (tid < 128) sgate[tid] = bx2v;
        }
        __syncthreads();

        // ---- ea-GEMM (K=16) + fused gather + silu -> tile (perm tf32) ----
        {
            float acc[4][4];
#pragma unroll
            for (int nt = 0; nt < 4; nt++)
#pragma unroll
                for (int l = 0; l < 4; l++) acc[nt][l] = 0.f;
            const float* a0p = sEA + (mrow + g) * 20 + tg;
            const float* b0p = wtE + (ncol + g) * 16 + 2 * tg;
#pragma unroll
            for (int kk = 0; kk < 2; kk++) {
                int k0 = kk * 8;
                unsigned a[4];
                a[0] = f2tf(a0p[k0]);
                a[1] = f2tf(a0p[8 * 20 + k0]);
                a[2] = f2tf(a0p[k0 + 4]);
                a[3] = f2tf(a0p[8 * 20 + k0 + 4]);
#pragma unroll
                for (int nt = 0; nt < 4; nt++) {
                    float2 b = *(const float2*)(b0p + nt * 8 * 16 + k0);
                    unsigned bb[2] = {__float_as_uint(b.x), __float_as_uint(b.y)};
                    mma8(acc[nt], a, bb);
                }
            }
#pragma unroll
            for (int rr = 0; rr < 2; rr++) {
                int row = mrow + g + rr * 8;
                int si = ((const int*)sEA)[row * 20 + 17];
                int di = ((const int*)sEA)[row * 20 + 18];
                float dist = sEA[row * 20 + 16];
#pragma unroll
                for (int nt = 0; nt < 4; nt++) {
                    int c = ncol + nt * 8 + tg * 2;
                    float2 a2 = *(const float2*)&g_A[si * 128 + c];
                    float2 b2 = *(const float2*)&g_B[di * 128 + c];
                    float2 w2 = *(const float2*)&wds[c];
                    float2 be = *(const float2*)&be1s[c];
                    float v0 = acc[nt][rr * 2 + 0] + dist * w2.x + be.x + a2.x + b2.x;
                    float v1 = acc[nt][rr * 2 + 1] + dist * w2.y + be.y + a2.y + b2.y;
                    int base = row * SP + (c & ~7);
                    tile[base + kpos(c & 7) - (c & ~7 & 7)] = 0.f;  // dummy removed below
                }
            }
            // (restructured stores to avoid dead code above)
#pragma unroll
            for (int rr = 0; rr < 2; rr++) {
                int row = mrow + g + rr * 8;
                int si = ((const int*)sEA)[row * 20 + 17];
                int di = ((const int*)sEA)[row * 20 + 18];
                float dist = sEA[row * 20 + 16];
#pragma unroll
                for (int nt = 0; nt < 4; nt++) {
                    int c = ncol + nt * 8 + tg * 2;
                    float2 a2 = *(const float2*)&g_A[si * 128 + c];
                    float2 b2 = *(const float2*)&g_B[di * 128 + c];
                    float2 w2 = *(const float2*)&wds[c];
                    float2 be = *(const float2*)&be1s[c];
                    float v0 = acc[nt][rr * 2 + 0] + dist * w2.x + be.x + a2.x + b2.x;
                    float v1 = acc[nt][rr * 2 + 1] + dist * w2.y + be.y + a2.y + b2.y;
                    int base = row * SP + (c & ~7);
                    int j = c & 7;  // = tg*2
                    tile[base + (j & 3) * 2 + (j >> 2)] = __uint_as_float(f2tf(siluf(v0)));
                    tile[base + ((j + 1) & 3) * 2 + ((j + 1) >> 2)] =
                        __uint_as_float(f2tf(siluf(v1)));
                }
            }
        }
        __syncthreads();

        // ---- GEMM1: mm = s @ We2 + be2 ----
        float accm[4][4];
#pragma unroll
        for (int nt = 0; nt < 4; nt++) {
            int cb = ncol + nt * 8 + tg * 2;
            float b0v = be2s[cb], b1v = be2s[cb + 1];
            accm[nt][0] = b0v;
            accm[nt][1] = b1v;
            accm[nt][2] = b0v;
            accm[nt][3] = b1v;
        }
        gemm_kloop16p(tile, wt2, mrow, ncol, lane, accm);

        // agg scatter straight from accumulators (fire-and-forget)
#pragma unroll
        for (int rr = 0; rr < 2; rr++) {
            int row = mrow + g + rr * 8;
            int di = ((const int*)sEA)[row * 20 + 18];
#pragma unroll
            for (int nt = 0; nt < 4; nt++) {
                int c = ncol + nt * 8 + tg * 2;
                asm volatile("red.global.add.v2.f32 [%0], {%1,%2};"
                             :: "l"(&g_agg[di * 128 + c]),
                                "f"(accm[nt][rr * 2 + 0]), "f"(accm[nt][rr * 2 + 1])
                             : "memory");
            }
        }
        __syncthreads();  // all warps done reading s before overwrite

        // store mm into tile (perm tf32)
#pragma unroll
        for (int rr = 0; rr < 2; rr++) {
            int row = mrow + g + rr * 8;
#pragma unroll
            for (int nt = 0; nt < 4; nt++) {
                int c = ncol + nt * 8 + tg * 2;
                int base = row * SP + (c & ~7);
                int j = c & 7;
                tile[base + (j & 3) * 2 + (j >> 2)] =
                    __uint_as_float(f2tf(accm[nt][rr * 2 + 0]));
                tile[base + ((j + 1) & 3) * 2 + ((j + 1) >> 2)] =
                    __uint_as_float(f2tf(accm[nt][rr * 2 + 1]));
            }
        }
        __syncthreads();

        // ---- GEMM2: gate = sum silu(mm@Wx1+bx1)*wx2 ----
        {
            float acc[4][4];
#pragma unroll
            for (int nt = 0; nt < 4; nt++) {
                int cb = ncol + nt * 8 + tg * 2;
                float b0v = bx1s[cb], b1v = bx1s[cb + 1];
                acc[nt][0] = b0v;
                acc[nt][1] = b1v;
                acc[nt][2] = b0v;
                acc[nt][3] = b1v;
            }
            gemm_kloop16p(tile, wtx, mrow, ncol, lane, acc);
            float p0 = 0.f, p1 = 0.f;
#pragma unroll
            for (int nt = 0; nt < 4; nt++) {
                int cb = ncol + nt * 8 + tg * 2;
                float w0 = wx2s[cb], w1 = wx2s[cb + 1];
                p0 += siluf(acc[nt][0]) * w0 + siluf(acc[nt][1]) * w1;
                p1 += siluf(acc[nt][2]) * w0 + siluf(acc[nt][3]) * w1;
            }
            p0 += __shfl_xor_sync(0xffffffffu, p0, 1);
            p0 += __shfl_xor_sync(0xffffffffu, p0, 2);
            p1 += __shfl_xor_sync(0xffffffffu, p1, 1);
            p1 += __shfl_xor_sync(0xffffffffu, p1, 2);
            if (tg == 0) {
                atomicAdd(&sgate[mrow + g], p0);
                atomicAdd(&sgate[mrow + g + 8], p1);
            }
        }
        __syncthreads();

        // ---- x scatter ----
        if (tid < 128) {
            int si = ((const int*)sEA)[tid * 20 + 17];
            int di = ((const int*)sEA)[tid * 20 + 18];
            float dx = x[di * 3 + 0] - x[si * 3 + 0];
            float dy = x[di * 3 + 1] - x[si * 3 + 1];
            float dz = x[di * 3 + 2] - x[si * 3 + 2];
            float rn = __fdividef(1.0f, sqrtf(dx * dx + dy * dy + dz * dz) + 1e-9f);
            float gte = sgate[tid];
            atomicAdd(&outx[di * 3 + 0], dx * rn * gte);
            atomicAdd(&outx[di * 3 + 1], dy * rn * gte);
            atomicAdd(&outx[di * 3 + 2], dz * rn * gte);
        }
        __syncthreads();
    }
}

// ---------------- node update: LN(h + phi_h([h,agg])) -----------------------
__global__ __launch_bounds__(256, 1) void k_node_upd(
    const float* __restrict__ h, const float* __restrict__ Wh1,
    const float* __restrict__ bh1, const float* __restrict__ Wh2,
    const float* __restrict__ bh2, const float* __restrict__ lng,
    const float* __restrict__ lnb, float* __restrict__ outh) {
    extern __shared__ float sm[];
    float* ht = sm;
    float* at = ht + 128 * SP;
    float* wt = at + 128 * SP;
    float* bh1s = wt + 128 * SP;
    float* bh2s = bh1s + 128;
    float* lngs = bh2s + 128;
    float* lnbs = lngs + 128;
    float* ssum = lnbs + 128;
    float* ssq = ssum + 128;

    int tid = threadIdx.x, lane = tid & 31, warp = tid >> 5;
    int n0 = blockIdx.x * 128;

    if (tid < 128) {
        bh1s[tid] = bh1[tid];
        bh2s[tid] = bh2[tid];
        lngs[tid] = lng[tid];
        lnbs[tid] = lnb[tid];
        ssum[tid] = 0.f;
        ssq[tid] = 0.f;
    }
#pragma unroll
    for (int v = 0; v < 16; v++) {
        int f = v * 256 + tid;
        int r = f >> 5, c4 = (f & 31) * 4;
        float4 hv = make_float4(0.f, 0.f, 0.f, 0.f);
        float4 av = make_float4(0.f, 0.f, 0.f, 0.f);
        if (n0 + r < NN) {
            hv = *(const float4*)&h[(n0 + r) * 128 + c4];
            av = *(const float4*)&g_agg[(n0 + r) * 128 + c4];
        }
        *(float4*)&ht[r * SP + c4] = hv;
        *(float4*)&at[r * SP + c4] = av;
    }
    stage_wt256(wt, Wh1, tid);
    __syncthreads();

    int mrow = (warp >> 1) * 32, ncol = (warp & 1) * 64;
    int g = lane >> 2, tg = lane & 3;

    float acc[2][8][4];
    acc_init_bias(acc, bh1s, ncol, tg);
    gemm_kloop(ht, wt, mrow, ncol, lane, acc);
    __syncthreads();
    stage_wt256(wt, Wh1 + 128 * 128, tid);
    __syncthreads();
    gemm_kloop(at, wt, mrow, ncol, lane, acc);
    __syncthreads();

#pragma unroll
    for (int mt = 0; mt < 2; mt++)
#pragma unroll
        for (int nt = 0; nt < 8; nt++) {
            int r = mrow + mt * 16 + g;
            int cb = ncol + nt * 8 + tg * 2;
            *(float2*)&at[r * SP + cb] =
                make_float2(siluf(acc[mt][nt][0]), siluf(acc[mt][nt][1]));
            *(float2*)&at[(r + 8) * SP + cb] =
                make_float2(siluf(acc[mt][nt][2]), siluf(acc[mt][nt][3]));
        }
    __syncthreads();
    stage_wt256(wt, Wh2, tid);
    __syncthreads();

    float acc2[2][8][4];
    acc_init_bias(acc2, bh2s, ncol, tg);
    gemm_kloop(at, wt, mrow, ncol, lane, acc2);

    float vsum[4] = {0.f, 0.f, 0.f, 0.f};
    float vsq[4] = {0.f, 0.f, 0.f, 0.f};
#pragma unroll
    for (int mt = 0; mt < 2; mt++)
#pragma unroll
        for (int nt = 0; nt < 8; nt++) {
            int r = mrow + mt * 16 + g;
            int cb = ncol + nt * 8 + tg * 2;
            float v0 = ht[r * SP + cb] + acc2[mt][nt][0];
            float v1 = ht[r * SP + cb + 1] + acc2[mt][nt][1];
            float v2 = ht[(r + 8) * SP + cb] + acc2[mt][nt][2];
            float v3 = ht[(r + 8) * SP + cb + 1] + acc2[mt][nt][3];
            acc2[mt][nt][0] = v0; acc2[mt][nt][1] = v1;
            acc2[mt][nt][2] = v2; acc2[mt][nt][3] = v3;
            vsum[mt * 2 + 0] += v0 + v1;
            vsq[mt * 2 + 0] += v0 * v0 + v1 * v1;
            vsum[mt * 2 + 1] += v2 + v3;
            vsq[mt * 2 + 1] += v2 * v2 + v3 * v3;
        }
#pragma unroll
    for (int i = 0; i < 4; i++) {
        vsum[i] += __shfl_xor_sync(0xffffffffu, vsum[i], 1);
        vsum[i] += __shfl_xor_sync(0xffffffffu, vsum[i], 2);
        vsq[i] += __shfl_xor_sync(0xffffffffu, vsq[i], 1);
        vsq[i] += __shfl_xor_sync(0xffffffffu, vsq[i], 2);
    }
    {
        float sv = (tg == 0) ? vsum[0] : (tg == 1) ? vsum[1] : (tg == 2) ? vsum[2] : vsum[3];
        float qv = (tg == 0) ? vsq[0] : (tg == 1) ? vsq[1] : (tg == 2) ? vsq[2] : vsq[3];
        int row = mrow + tg * 8 + g;
        atomicAdd(&ssum[row], sv);
        atomicAdd(&ssq[row], qv);
    }
    __syncthreads();

#pragma unroll
    for (int mt = 0; mt < 2; mt++)
#pragma unroll
        for (int nt = 0; nt < 8; nt++) {
            int r = mrow + mt * 16 + g;
            int cb = ncol + nt * 8 + tg * 2;
            float mean0 = ssum[r] * (1.0f / 128.0f);
            float var0 = ssq[r] * (1.0f / 128.0f) - mean0 * mean0;
            float rstd0 = rsqrtf(var0 + 1e-5f);
            float mean1 = ssum[r + 8] * (1.0f / 128.0f);
            float var1 = ssq[r + 8] * (1.0f / 128.0f) - mean1 * mean1;
            float rstd1 = rsqrtf(var1 + 1e-5f);
            float g0 = lngs[cb], g1 = lngs[cb + 1];
            float b0 = lnbs[cb], b1 = lnbs[cb + 1];
            if (n0 + r < NN)
                *(float2*)&outh[(n0 + r) * 128 + cb] = make_float2(
                    (acc2[mt][nt][0] - mean0) * rstd0 * g0 + b0,
                    (acc2[mt][nt][1] - mean0) * rstd0 * g1 + b1);
            if (n0 + r + 8 < NN)
                *(float2*)&outh[(n0 + r + 8) * 128 + cb] = make_float2(
                    (acc2[mt][nt][2] - mean1) * rstd1 * g0 + b0,
                    (acc2[mt][nt][3] - mean1) * rstd1 * g1 + b1);
        }
}

// ---------------- launcher ---------------------------------------------------
extern "C" void kernel_launch(void* const* d_in, const int* in_sizes, int n_in,
                              void* d_out, int out_size) {
    const float* h = (const float*)d_in[0];
    const float* x = (const float*)d_in[1];
    const void* ei = d_in[2];
    const float* ea = (const float*)d_in[3];
    const float* We1 = (const float*)d_in[4];
    const float* be1 = (const float*)d_in[5];
    const float* We2 = (const float*)d_in[6];
    const float* be2 = (const float*)d_in[7];
    const float* Wh1 = (const float*)d_in[8];
    const float* bh1 = (const float*)d_in[9];
    const float* Wh2 = (const float*)d_in[10];
    const float* bh2 = (const float*)d_in[11];
    const float* Wx1 = (const float*)d_in[12];
    const float* bx1 = (const float*)d_in[13];
    const float* Wx2 = (const float*)d_in[14];
    const float* bx2 = (const float*)d_in[15];
    const float* lng = (const float*)d_in[16];
    const float* lnb = (const float*)d_in[17];

    float* outh = (float*)d_out;
    float* outx = outh + (size_t)NN * 128;

    const int SMEM_EDGE = (3 * 128 * SP + 128 * 20 + 128 * 16 + 6 * 128) * 4;  // 230400
    const int SMEM_PRE = (3 * 128 * SP) * 4;                                    // 208896
    const int SMEM_UPD = (3 * 128 * SP + 6 * 128) * 4;                          // 211968
    cudaFuncSetAttribute(k_edge, cudaFuncAttributeMaxDynamicSharedMemorySize, SMEM_EDGE);
    cudaFuncSetAttribute(k_node_pre, cudaFuncAttributeMaxDynamicSharedMemorySize, SMEM_PRE);
    cudaFuncSetAttribute(k_node_upd, cudaFuncAttributeMaxDynamicSharedMemorySize, SMEM_UPD);

    k_detect<<<1, 32>>>(ei);
    k_convert<<<(EE + 255) / 256, 256>>>(ei);
    k_init<<<1024, 256>>>(x, outx);
    k_node_pre<<<PGRID, 1024, SMEM_PRE>>>(h, We1);
    k_edge<<<PGRID, 1024, SMEM_EDGE>>>(x, ea, We1, be1, We2, be2, Wx1, bx1, Wx2,
                                       bx2, outx);
    k_node_upd<<<(NN + 127) / 128, 256, SMEM_UPD>>>(h, Wh1, bh1, Wh2, bh2, lng, lnb,
                                                    outh);
}